// round 8
// baseline (speedup 1.0000x reference)
#include <cuda_runtime.h>
#include <cuda_bf16.h>
#include <cuda_fp16.h>
#include <cstdint>

// Problem constants
constexpr int kB  = 2;
constexpr int kS  = 2048;
constexpr int kH  = 512;
constexpr int kNH = 8;
constexpr int kDK = 64;
constexpr int kM  = kB * kS;       // 4096
constexpr float kScale = 0.125f;   // 1/sqrt(64)

constexpr int kHE = kB * kNH * kS * kDK;  // elems per head tensor (2M)
constexpr int kIE = kM * kH;              // elems per input (2M)
constexpr int kWE = kH * kH;              // elems per weight (256K)

// Scratch (device globals; no allocations allowed)
__device__ __nv_bfloat16 g_qhi[kHE], g_qlo[kHE];
__device__ __nv_bfloat16 g_khi[kHE], g_klo[kHE];
__device__ __half        g_vhi[kHE], g_vlo[kHE];   // V in fp16 hi/lo
__device__ __nv_bfloat16 g_ctxh[kIE], g_ctxl[kIE]; // ctx bf16 hi/lo [B*S, H]
__device__ __nv_bfloat16 g_inh[3 * kIE], g_inl[3 * kIE];   // q,k,v inputs split
__device__ __nv_bfloat16 g_wh[4 * kWE], g_wl[4 * kWE];     // Wq,Wk,Wv,Wo split

// ---------------------------------------------------------------------------
// MMA / async-copy helpers
// ---------------------------------------------------------------------------
__device__ __forceinline__ uint32_t smaddr(const void* p) {
    return (uint32_t)__cvta_generic_to_shared(p);
}
__device__ __forceinline__ void ldsm_x4(uint32_t* r, uint32_t a) {
    asm volatile("ldmatrix.sync.aligned.m8n8.x4.shared.b16 {%0,%1,%2,%3},[%4];"
        : "=r"(r[0]), "=r"(r[1]), "=r"(r[2]), "=r"(r[3]) : "r"(a));
}
__device__ __forceinline__ void ldsm_x4t(uint32_t* r, uint32_t a) {
    asm volatile("ldmatrix.sync.aligned.m8n8.x4.trans.shared.b16 {%0,%1,%2,%3},[%4];"
        : "=r"(r[0]), "=r"(r[1]), "=r"(r[2]), "=r"(r[3]) : "r"(a));
}
__device__ __forceinline__ void mma_bf16(float* c, const uint32_t* a,
                                         const uint32_t* b) {
    asm volatile(
        "mma.sync.aligned.m16n8k16.row.col.f32.bf16.bf16.f32 "
        "{%0,%1,%2,%3},{%4,%5,%6,%7},{%8,%9},{%0,%1,%2,%3};"
        : "+f"(c[0]), "+f"(c[1]), "+f"(c[2]), "+f"(c[3])
        : "r"(a[0]), "r"(a[1]), "r"(a[2]), "r"(a[3]), "r"(b[0]), "r"(b[1]));
}
__device__ __forceinline__ void mma_fp16(float* c, const uint32_t* a,
                                         const uint32_t* b) {
    asm volatile(
        "mma.sync.aligned.m16n8k16.row.col.f32.f16.f16.f32 "
        "{%0,%1,%2,%3},{%4,%5,%6,%7},{%8,%9},{%0,%1,%2,%3};"
        : "+f"(c[0]), "+f"(c[1]), "+f"(c[2]), "+f"(c[3])
        : "r"(a[0]), "r"(a[1]), "r"(a[2]), "r"(a[3]), "r"(b[0]), "r"(b[1]));
}
__device__ __forceinline__ uint32_t pack_bf16(float x, float y) {
    __nv_bfloat162 h = __floats2bfloat162_rn(x, y);
    return *reinterpret_cast<uint32_t*>(&h);
}
__device__ __forceinline__ uint32_t pack_fp16(float x, float y) {
    __half2 h = __floats2half2_rn(x, y);
    return *reinterpret_cast<uint32_t*>(&h);
}
__device__ __forceinline__ void cp16(uint32_t dst, const void* src) {
    asm volatile("cp.async.cg.shared.global [%0],[%1],16;"
        :: "r"(dst), "l"(src));
}
__device__ __forceinline__ void cp_commit() {
    asm volatile("cp.async.commit_group;");
}
template <int N>
__device__ __forceinline__ void cp_wait() {
    asm volatile("cp.async.wait_group %0;" :: "n"(N));
}

// ---------------------------------------------------------------------------
// Conversion: fp32 -> bf16 hi/lo. One launch; blockIdx.y selects segment.
// Segments 0..2: inputs q,k,v (kIE each). 3..6: weights Wq,Wk,Wv,Wo (kWE).
// ---------------------------------------------------------------------------
__global__ __launch_bounds__(256) void cvt_kernel(
    const float* __restrict__ q, const float* __restrict__ k,
    const float* __restrict__ v,
    const float* __restrict__ Wq, const float* __restrict__ Wk,
    const float* __restrict__ Wv, const float* __restrict__ Wo)
{
    const int seg = blockIdx.y;
    const float* src;
    __nv_bfloat16 *dh, *dl;
    int n;
    if (seg < 3) {
        src = (seg == 0) ? q : (seg == 1) ? k : v;
        dh = g_inh + (size_t)seg * kIE;
        dl = g_inl + (size_t)seg * kIE;
        n = kIE;
    } else {
        const int wi = seg - 3;
        src = (wi == 0) ? Wq : (wi == 1) ? Wk : (wi == 2) ? Wv : Wo;
        dh = g_wh + (size_t)wi * kWE;
        dl = g_wl + (size_t)wi * kWE;
        n = kWE;
    }
    const int idx4 = (blockIdx.x * 256 + threadIdx.x) << 2;
    if (idx4 < n) {
        float4 val = *(const float4*)&src[idx4];
        __nv_bfloat162 h01 = __floats2bfloat162_rn(val.x, val.y);
        __nv_bfloat162 h23 = __floats2bfloat162_rn(val.z, val.w);
        *(__nv_bfloat162*)&dh[idx4]     = h01;
        *(__nv_bfloat162*)&dh[idx4 + 2] = h23;
        *(uint32_t*)&dl[idx4]     = pack_bf16(val.x - __low2float(h01),
                                              val.y - __high2float(h01));
        *(uint32_t*)&dl[idx4 + 2] = pack_bf16(val.z - __low2float(h23),
                                              val.w - __high2float(h23));
    }
}

// ---------------------------------------------------------------------------
// Tensor-core GEMM on pre-split bf16 hi/lo inputs, cp.async 2-stage pipeline.
// Y[4096, 512] = X @ W + bias. CTA 128x128, K-step 32, 8 warps (4M x 2N).
// mode 0/1: bf16 hi/lo head layout (0 = scaled Q). mode 2: fp16 hi/lo (V).
// mode 3: fp32 out + bias.
// ---------------------------------------------------------------------------
constexpr int kXStr = 40;    // 32-wide X k-tile row stride
constexpr int kWStr = 136;   // 128-wide W n-tile row stride
constexpr int kXTile = 128 * kXStr;   // elems per X array per stage
constexpr int kWTile = 32 * kWStr;
constexpr int kGStage = 2 * kXTile + 2 * kWTile;   // Xh,Xl,Wh,Wl

__device__ __forceinline__ void gemm_core(
    const __nv_bfloat16* __restrict__ Xh, const __nv_bfloat16* __restrict__ Xl,
    const __nv_bfloat16* __restrict__ Wh, const __nv_bfloat16* __restrict__ Wl,
    const float* __restrict__ bias, float* __restrict__ Yout, int mode)
{
    extern __shared__ __nv_bfloat16 gsm[];

    const int tid  = threadIdx.x;
    const int lane = tid & 31, w = tid >> 5;
    const int wm = w >> 1, wn = w & 1;
    const int m0 = blockIdx.y << 7, n0 = blockIdx.x << 7;

    float acc[2][8][4];
#pragma unroll
    for (int mi = 0; mi < 2; ++mi)
#pragma unroll
        for (int jn = 0; jn < 8; ++jn)
#pragma unroll
            for (int i = 0; i < 4; ++i) acc[mi][jn][i] = 0.f;

    // staging: X 512 chunks/array (row=c>>2, col=(c&3)*8); W 512 (row=c>>4,col=(c&15)*8)
    const int xc0 = tid << 1;          // 2 chunks per thread per array
    const int wc0 = tid << 1;

    auto stage_load = [&](int k0, int st) {
        __nv_bfloat16* s = gsm + st * kGStage;
        __nv_bfloat16* sXh = s;
        __nv_bfloat16* sXl = sXh + kXTile;
        __nv_bfloat16* sWh = sXl + kXTile;
        __nv_bfloat16* sWl = sWh + kWTile;
#pragma unroll
        for (int i = 0; i < 2; ++i) {
            const int c = xc0 + i;
            const int row = c >> 2, col = (c & 3) << 3;
            const size_t g = (size_t)(m0 + row) * kH + k0 + col;
            const int so = row * kXStr + col;
            cp16(smaddr(&sXh[so]), &Xh[g]);
            cp16(smaddr(&sXl[so]), &Xl[g]);
        }
#pragma unroll
        for (int i = 0; i < 2; ++i) {
            const int c = wc0 + i;
            const int row = c >> 4, col = (c & 15) << 3;
            const size_t g = (size_t)(k0 + row) * kH + n0 + col;
            const int so = row * kWStr + col;
            cp16(smaddr(&sWh[so]), &Wh[g]);
            cp16(smaddr(&sWl[so]), &Wl[g]);
        }
        cp_commit();
    };

    stage_load(0, 0);

    for (int t = 0; t < kH / 32; ++t) {
        if (t + 1 < kH / 32) {
            stage_load((t + 1) << 5, (t + 1) & 1);
            cp_wait<1>();
        } else {
            cp_wait<0>();
        }
        __syncthreads();

        const __nv_bfloat16* s = gsm + (t & 1) * kGStage;
        const __nv_bfloat16* sXh = s;
        const __nv_bfloat16* sXl = sXh + kXTile;
        const __nv_bfloat16* sWh = sXl + kXTile;
        const __nv_bfloat16* sWl = sWh + kWTile;

#pragma unroll
        for (int k16 = 0; k16 < 2; ++k16) {
            uint32_t afh[2][4], afl[2][4];
#pragma unroll
            for (int mi = 0; mi < 2; ++mi) {
                const int row = (wm << 5) + (mi << 4) + (lane & 15);
                const int col = (k16 << 4) + ((lane >> 4) << 3);
                ldsm_x4(afh[mi], smaddr(&sXh[row * kXStr + col]));
                ldsm_x4(afl[mi], smaddr(&sXl[row * kXStr + col]));
            }
#pragma unroll
            for (int jp = 0; jp < 4; ++jp) {
                const int brow = (k16 << 4) + (lane & 15);
                const int bcol = (wn << 6) + (jp << 4) + ((lane >> 4) << 3);
                uint32_t bh[4], bl[4];
                ldsm_x4t(bh, smaddr(&sWh[brow * kWStr + bcol]));
                ldsm_x4t(bl, smaddr(&sWl[brow * kWStr + bcol]));
#pragma unroll
                for (int mi = 0; mi < 2; ++mi) {
                    mma_bf16(acc[mi][2 * jp],     afh[mi], bh);
                    mma_bf16(acc[mi][2 * jp + 1], afh[mi], bh + 2);
                    mma_bf16(acc[mi][2 * jp],     afl[mi], bh);
                    mma_bf16(acc[mi][2 * jp + 1], afl[mi], bh + 2);
                    mma_bf16(acc[mi][2 * jp],     afh[mi], bl);
                    mma_bf16(acc[mi][2 * jp + 1], afh[mi], bl + 2);
                }
            }
        }
        __syncthreads();   // all reads of stage t done before t+1 overwrites it
    }

    __nv_bfloat16* oh = (mode == 0) ? g_qhi : g_khi;
    __nv_bfloat16* ol = (mode == 0) ? g_qlo : g_klo;

#pragma unroll
    for (int jn = 0; jn < 8; ++jn) {
        const int n = n0 + (wn << 6) + (jn << 3) + ((lane & 3) << 1);
        float2 bv = *(const float2*)&bias[n];
#pragma unroll
        for (int mi = 0; mi < 2; ++mi) {
#pragma unroll
            for (int half = 0; half < 2; ++half) {
                const int m = m0 + (wm << 5) + (mi << 4) + (lane >> 2) + (half << 3);
                float v0 = acc[mi][jn][half * 2 + 0] + bv.x;
                float v1 = acc[mi][jn][half * 2 + 1] + bv.y;
                if (mode == 0) { v0 *= kScale; v1 *= kScale; }
                if (mode < 3) {
                    const int b_ = m >> 11;
                    const int s_ = m & (kS - 1);
                    const int h_ = n >> 6;
                    const int d_ = n & (kDK - 1);
                    size_t off = (((size_t)(b_ * kNH + h_)) * kS + s_) * kDK + d_;
                    if (mode < 2) {
                        __nv_bfloat162 hv = __floats2bfloat162_rn(v0, v1);
                        *(__nv_bfloat162*)&oh[off] = hv;
                        *(uint32_t*)&ol[off] = pack_bf16(v0 - __low2float(hv),
                                                         v1 - __high2float(hv));
                    } else {
                        __half2 hv = __floats2half2_rn(v0, v1);
                        *(__half2*)&g_vhi[off] = hv;
                        float h0f = __half2float(__low2half(hv));
                        float h1f = __half2float(__high2half(hv));
                        *(uint32_t*)&g_vlo[off] = pack_fp16(v0 - h0f, v1 - h1f);
                    }
                } else {
                    *(float2*)&Yout[(size_t)m * kH + n] = make_float2(v0, v1);
                }
            }
        }
    }
}

__global__ __launch_bounds__(256, 2) void qkv_gemm(
    const float* __restrict__ bq, const float* __restrict__ bk,
    const float* __restrict__ bv)
{
    const int mode = blockIdx.z;
    const float* B = (mode == 0) ? bq : (mode == 1) ? bk : bv;
    gemm_core(g_inh + (size_t)mode * kIE, g_inl + (size_t)mode * kIE,
              g_wh + (size_t)mode * kWE, g_wl + (size_t)mode * kWE,
              B, nullptr, mode);
}

__global__ __launch_bounds__(256, 2) void out_gemm(
    const float* __restrict__ bo, float* __restrict__ out)
{
    gemm_core(g_ctxh, g_ctxl, g_wh + 3 * (size_t)kWE, g_wl + 3 * (size_t)kWE,
              bo, out, 3);
}

// ---------------------------------------------------------------------------
// Tensor-core flash attention (R7, unchanged except bf16 hi/lo ctx epilogue)
// ---------------------------------------------------------------------------
constexpr int kQStr = 72;
constexpr int kTileE = 128 * kQStr;
constexpr int kStageE = 4 * kTileE;           // stage = Kh,Kl,Vh,Vl

__global__ __launch_bounds__(256, 1) void attn_kernel(const float* __restrict__ bias)
{
    extern __shared__ __nv_bfloat16 sm[];
    __nv_bfloat16* Qh = sm;
    __nv_bfloat16* Ql = Qh + kTileE;
    __nv_bfloat16* KV = Ql + kTileE;

    const int bh = blockIdx.y;
    const int q0 = blockIdx.x << 7;
    const int tid = threadIdx.x;
    const int lane = tid & 31, w = tid >> 5;

    const size_t hb = (size_t)bh * kS * kDK;
    const __nv_bfloat16* Kgh = g_khi + hb;
    const __nv_bfloat16* Kgl = g_klo + hb;
    const __half*        Vgh = g_vhi + hb;
    const __half*        Vgl = g_vlo + hb;
    const float* Bp = bias + (size_t)bh * kS * kS + (size_t)q0 * kS;

    const int r = tid >> 3, c8 = (tid & 7) << 3;

    {
        __nv_bfloat16* Kh = KV;
        __nv_bfloat16* Kl = Kh + kTileE;
        __nv_bfloat16* Vh = Kl + kTileE;
        __nv_bfloat16* Vl = Vh + kTileE;
#pragma unroll
        for (int u = 0; u < 4; ++u) {
            const int row = r + (u << 5);
            const size_t g = (size_t)row * kDK + c8;
            const int so = row * kQStr + c8;
            cp16(smaddr(&Kh[so]), &Kgh[g]);
            cp16(smaddr(&Kl[so]), &Kgl[g]);
            cp16(smaddr(&Vh[so]), &Vgh[g]);
            cp16(smaddr(&Vl[so]), &Vgl[g]);
        }
        cp_commit();
    }

    {
        const __nv_bfloat16* Qgh = g_qhi + hb;
        const __nv_bfloat16* Qgl = g_qlo + hb;
#pragma unroll
        for (int u = 0; u < 4; ++u) {
            const int row = r + (u << 5);
            *(uint4*)&Qh[row * kQStr + c8] =
                *(const uint4*)&Qgh[(size_t)(q0 + row) * kDK + c8];
            *(uint4*)&Ql[row * kQStr + c8] =
                *(const uint4*)&Qgl[(size_t)(q0 + row) * kDK + c8];
        }
    }
    __syncthreads();

    uint32_t qfh[4][4], qfl[4][4];
    {
        const int r0 = w << 4;
#pragma unroll
        for (int kc = 0; kc < 4; ++kc) {
            const int row = r0 + (lane & 15);
            const int col = (kc << 4) + ((lane >> 4) << 3);
            ldsm_x4(qfh[kc], smaddr(&Qh[row * kQStr + col]));
            ldsm_x4(qfl[kc], smaddr(&Ql[row * kQStr + col]));
        }
    }

    float O[8][4];
#pragma unroll
    for (int j = 0; j < 8; j++)
#pragma unroll
        for (int i = 0; i < 4; i++) O[j][i] = 0.f;
    float l0 = 0.f, l1 = 0.f;

    const int rq = lane >> 2;
    const int cq = (lane & 3) << 1;
    const int krow_off = (lane & 7) + ((lane >> 4) << 3);
    const int kcol_off = ((lane >> 3) & 1) << 3;
    const int vrow_off = lane & 15;
    const int vcol_off = (lane >> 4) << 3;

    for (int t = 0; t < kS / 128; ++t) {
        if (t + 1 < kS / 128) {
            __nv_bfloat16* s = KV + ((t + 1) & 1) * kStageE;
            __nv_bfloat16* Kh = s;
            __nv_bfloat16* Kl = Kh + kTileE;
            __nv_bfloat16* Vh = Kl + kTileE;
            __nv_bfloat16* Vl = Vh + kTileE;
            const int k0n = (t + 1) << 7;
#pragma unroll
            for (int u = 0; u < 4; ++u) {
                const int row = r + (u << 5);
                const size_t g = (size_t)(k0n + row) * kDK + c8;
                const int so = row * kQStr + c8;
                cp16(smaddr(&Kh[so]), &Kgh[g]);
                cp16(smaddr(&Kl[so]), &Kgl[g]);
                cp16(smaddr(&Vh[so]), &Vgh[g]);
                cp16(smaddr(&Vl[so]), &Vgl[g]);
            }
            cp_commit();
            cp_wait<1>();
        } else {
            cp_wait<0>();
        }
        __syncthreads();

        __nv_bfloat16* s = KV + (t & 1) * kStageE;
        const __nv_bfloat16* Kh = s;
        const __nv_bfloat16* Kl = Kh + kTileE;
        const __nv_bfloat16* Vh = Kl + kTileE;
        const __nv_bfloat16* Vl = Vh + kTileE;
        const int k0 = t << 7;

        float acc[16][4];
#pragma unroll
        for (int jp = 0; jp < 8; ++jp) {
            float* a0 = acc[2 * jp];
            float* a1 = acc[2 * jp + 1];
            a0[0] = a0[1] = a0[2] = a0[3] = 0.f;
            a1[0] = a1[1] = a1[2] = a1[3] = 0.f;
            const int rowb = (jp << 4) + krow_off;
#pragma unroll
            for (int kc = 0; kc < 4; ++kc) {
                const int col = (kc << 4) + kcol_off;
                uint32_t kb[4], kbl[4];
                ldsm_x4(kb, smaddr(&Kh[rowb * kQStr + col]));
                mma_bf16(a0, qfh[kc], kb);
                mma_bf16(a1, qfh[kc], kb + 2);
                mma_bf16(a0, qfl[kc], kb);
                mma_bf16(a1, qfl[kc], kb + 2);
                ldsm_x4(kbl, smaddr(&Kl[rowb * kQStr + col]));
                mma_bf16(a0, qfh[kc], kbl);
                mma_bf16(a1, qfh[kc], kbl + 2);
            }
            const float* bp = Bp + (size_t)((w << 4) + rq) * kS + k0 + (jp << 4) + cq;
            float2 bA0 = *(const float2*)bp;
            float2 bB0 = *(const float2*)(bp + 8 * (size_t)kS);
            float2 bA1 = *(const float2*)(bp + 8);
            float2 bB1 = *(const float2*)(bp + 8 * (size_t)kS + 8);
            a0[0] += bA0.x; a0[1] += bA0.y; a0[2] += bB0.x; a0[3] += bB0.y;
            a1[0] += bA1.x; a1[1] += bA1.y; a1[2] += bB1.x; a1[3] += bB1.y;
        }

        uint32_t Ph[8][4];
#pragma unroll
        for (int j = 0; j < 16; ++j) {
            float p0 = __expf(acc[j][0]);
            float p1 = __expf(acc[j][1]);
            float p2 = __expf(acc[j][2]);
            float p3 = __expf(acc[j][3]);
            l0 += p0 + p1;
            l1 += p2 + p3;
            const int kc = j >> 1, bofs = (j & 1) << 1;
            Ph[kc][bofs]     = pack_fp16(p0, p1);
            Ph[kc][bofs + 1] = pack_fp16(p2, p3);
        }

#pragma unroll
        for (int jp = 0; jp < 4; ++jp) {
            float* o0 = O[2 * jp];
            float* o1 = O[2 * jp + 1];
            const int colb = (jp << 4) + vcol_off;
#pragma unroll
            for (int kc = 0; kc < 8; ++kc) {
                const int rowv = (kc << 4) + vrow_off;
                uint32_t vb[4], vbl[4];
                ldsm_x4t(vb, smaddr(&Vh[rowv * kQStr + colb]));
                mma_fp16(o0, Ph[kc], vb);
                mma_fp16(o1, Ph[kc], vb + 2);
                ldsm_x4t(vbl, smaddr(&Vl[rowv * kQStr + colb]));
                mma_fp16(o0, Ph[kc], vbl);
                mma_fp16(o1, Ph[kc], vbl + 2);
            }
        }
        __syncthreads();
    }

    // epilogue: ctx as bf16 hi/lo for the output GEMM
    l0 += __shfl_xor_sync(0xffffffffu, l0, 1);
    l0 += __shfl_xor_sync(0xffffffffu, l0, 2);
    l1 += __shfl_xor_sync(0xffffffffu, l1, 1);
    l1 += __shfl_xor_sync(0xffffffffu, l1, 2);
    const float inv0 = 1.f / l0, inv1 = 1.f / l1;

    const int b_ = bh >> 3, h_ = bh & 7;
    const int grow = q0 + (w << 4) + rq;
    const size_t base = ((size_t)b_ * kS + grow) * kH + h_ * kDK + cq;
#pragma unroll
    for (int jn = 0; jn < 8; ++jn) {
        {
            float v0 = O[jn][0] * inv0, v1 = O[jn][1] * inv0;
            __nv_bfloat162 hv = __floats2bfloat162_rn(v0, v1);
            *(__nv_bfloat162*)&g_ctxh[base + (jn << 3)] = hv;
            *(uint32_t*)&g_ctxl[base + (jn << 3)] =
                pack_bf16(v0 - __low2float(hv), v1 - __high2float(hv));
        }
        {
            float v0 = O[jn][2] * inv1, v1 = O[jn][3] * inv1;
            __nv_bfloat162 hv = __floats2bfloat162_rn(v0, v1);
            *(__nv_bfloat162*)&g_ctxh[base + (jn << 3) + 8 * kH] = hv;
            *(uint32_t*)&g_ctxl[base + (jn << 3) + 8 * kH] =
                pack_bf16(v0 - __low2float(hv), v1 - __high2float(hv));
        }
    }
}

// ---------------------------------------------------------------------------
extern "C" void kernel_launch(void* const* d_in, const int* in_sizes, int n_in,
                              void* d_out, int out_size)
{
    const float* q  = (const float*)d_in[0];
    const float* k  = (const float*)d_in[1];
    const float* v  = (const float*)d_in[2];
    const float* ab = (const float*)d_in[3];
    const float* Wq = (const float*)d_in[4];
    const float* bq = (const float*)d_in[5];
    const float* Wk = (const float*)d_in[6];
    const float* bk = (const float*)d_in[7];
    const float* Wv = (const float*)d_in[8];
    const float* bv = (const float*)d_in[9];
    const float* Wo = (const float*)d_in[10];
    const float* bo = (const float*)d_in[11];
    float* out = (float*)d_out;

    const int attn_smem = (2 * kTileE + 2 * kStageE) * 2;   // 184320 bytes
    const int gemm_smem = 2 * kGStage * 2;                  // 75776 bytes
    cudaFuncSetAttribute(attn_kernel,
                         cudaFuncAttributeMaxDynamicSharedMemorySize, attn_smem);
    cudaFuncSetAttribute(qkv_gemm,
                         cudaFuncAttributeMaxDynamicSharedMemorySize, gemm_smem);
    cudaFuncSetAttribute(out_gemm,
                         cudaFuncAttributeMaxDynamicSharedMemorySize, gemm_smem);

    dim3 blk(256);
    cvt_kernel<<<dim3(kIE / 1024, 7), blk>>>(q, k, v, Wq, Wk, Wv, Wo);
    qkv_gemm<<<dim3(kH / 128, kM / 128, 3), blk, gemm_smem>>>(bq, bk, bv);
    attn_kernel<<<dim3(kS / 128, kB * kNH), blk, attn_smem>>>(ab);
    out_gemm<<<dim3(kH / 128, kM / 128), blk, gemm_smem>>>(bo, out);
}

// round 9
// speedup vs baseline: 1.1019x; 1.1019x over previous
#include <cuda_runtime.h>
#include <cuda_bf16.h>
#include <cuda_fp16.h>
#include <cstdint>

// Problem constants
constexpr int kB  = 2;
constexpr int kS  = 2048;
constexpr int kH  = 512;
constexpr int kNH = 8;
constexpr int kDK = 64;
constexpr int kM  = kB * kS;       // 4096
constexpr float kScale = 0.125f;   // 1/sqrt(64)

constexpr int kHE = kB * kNH * kS * kDK;  // elems per head tensor (2M)

// Scratch (device globals; no allocations allowed)
__device__ __nv_bfloat16 g_qhi[kHE], g_qlo[kHE];
__device__ __nv_bfloat16 g_khi[kHE], g_klo[kHE];
__device__ __half        g_vhi[kHE], g_vlo[kHE];   // V in fp16 hi/lo
__device__ float g_ctx[kM * kH];          // [B*S, H]

// ---------------------------------------------------------------------------
// MMA / async-copy helpers
// ---------------------------------------------------------------------------
__device__ __forceinline__ uint32_t smaddr(const void* p) {
    return (uint32_t)__cvta_generic_to_shared(p);
}
__device__ __forceinline__ void ldsm_x4(uint32_t* r, uint32_t a) {
    asm volatile("ldmatrix.sync.aligned.m8n8.x4.shared.b16 {%0,%1,%2,%3},[%4];"
        : "=r"(r[0]), "=r"(r[1]), "=r"(r[2]), "=r"(r[3]) : "r"(a));
}
__device__ __forceinline__ void ldsm_x4t(uint32_t* r, uint32_t a) {
    asm volatile("ldmatrix.sync.aligned.m8n8.x4.trans.shared.b16 {%0,%1,%2,%3},[%4];"
        : "=r"(r[0]), "=r"(r[1]), "=r"(r[2]), "=r"(r[3]) : "r"(a));
}
__device__ __forceinline__ void mma_bf16(float* c, const uint32_t* a,
                                         const uint32_t* b) {
    asm volatile(
        "mma.sync.aligned.m16n8k16.row.col.f32.bf16.bf16.f32 "
        "{%0,%1,%2,%3},{%4,%5,%6,%7},{%8,%9},{%0,%1,%2,%3};"
        : "+f"(c[0]), "+f"(c[1]), "+f"(c[2]), "+f"(c[3])
        : "r"(a[0]), "r"(a[1]), "r"(a[2]), "r"(a[3]), "r"(b[0]), "r"(b[1]));
}
__device__ __forceinline__ void mma_fp16(float* c, const uint32_t* a,
                                         const uint32_t* b) {
    asm volatile(
        "mma.sync.aligned.m16n8k16.row.col.f32.f16.f16.f32 "
        "{%0,%1,%2,%3},{%4,%5,%6,%7},{%8,%9},{%0,%1,%2,%3};"
        : "+f"(c[0]), "+f"(c[1]), "+f"(c[2]), "+f"(c[3])
        : "r"(a[0]), "r"(a[1]), "r"(a[2]), "r"(a[3]), "r"(b[0]), "r"(b[1]));
}
__device__ __forceinline__ uint32_t pack_bf16(float x, float y) {
    __nv_bfloat162 h = __floats2bfloat162_rn(x, y);
    return *reinterpret_cast<uint32_t*>(&h);
}
__device__ __forceinline__ uint32_t pack_fp16(float x, float y) {
    __half2 h = __floats2half2_rn(x, y);
    return *reinterpret_cast<uint32_t*>(&h);
}
__device__ __forceinline__ void split4(float4 v, uint32_t& h0, uint32_t& h1,
                                       uint32_t& l0, uint32_t& l1) {
    __nv_bfloat162 a = __floats2bfloat162_rn(v.x, v.y);
    __nv_bfloat162 b = __floats2bfloat162_rn(v.z, v.w);
    h0 = *reinterpret_cast<uint32_t*>(&a);
    h1 = *reinterpret_cast<uint32_t*>(&b);
    l0 = pack_bf16(v.x - __low2float(a), v.y - __high2float(a));
    l1 = pack_bf16(v.z - __low2float(b), v.w - __high2float(b));
}
__device__ __forceinline__ void cp16(uint32_t dst, const void* src) {
    asm volatile("cp.async.cg.shared.global [%0],[%1],16;"
        :: "r"(dst), "l"(src));
}
__device__ __forceinline__ void cp_commit() {
    asm volatile("cp.async.commit_group;");
}
template <int N>
__device__ __forceinline__ void cp_wait() {
    asm volatile("cp.async.wait_group %0;" :: "n"(N));
}

// ---------------------------------------------------------------------------
// Tensor-core GEMM (R7 version, known-good)
// ---------------------------------------------------------------------------
constexpr int kXStr = 40;
constexpr int kWStr = 136;

__device__ __forceinline__ void gemm_core(
    const float* __restrict__ X, const float* __restrict__ W,
    const float* __restrict__ bias, float* __restrict__ Yout, int mode)
{
    __shared__ __nv_bfloat16 Xh[128 * kXStr], Xl[128 * kXStr];
    __shared__ __nv_bfloat16 Wh[32 * kWStr],  Wl[32 * kWStr];

    const int tid  = threadIdx.x;
    const int lane = tid & 31, w = tid >> 5;
    const int wm = w >> 1, wn = w & 1;
    const int m0 = blockIdx.y << 7, n0 = blockIdx.x << 7;

    float acc[2][8][4];
#pragma unroll
    for (int mi = 0; mi < 2; ++mi)
#pragma unroll
        for (int jn = 0; jn < 8; ++jn)
#pragma unroll
            for (int i = 0; i < 4; ++i) acc[mi][jn][i] = 0.f;

    const int xr = tid >> 3, xc = (tid & 7) << 2;
    const int wr = tid >> 5, wc = (tid & 31) << 2;

    float4 xs[4], ws[4];
#pragma unroll
    for (int p = 0; p < 4; ++p) {
        xs[p] = *(const float4*)&X[(size_t)(m0 + xr + (p << 5)) * kH + xc];
        ws[p] = *(const float4*)&W[(size_t)(wr + (p << 3)) * kH + n0 + wc];
    }

    for (int k0 = 0; k0 < kH; k0 += 32) {
        __syncthreads();
#pragma unroll
        for (int p = 0; p < 4; ++p) {
            uint32_t h0, h1, l0, l1;
            split4(xs[p], h0, h1, l0, l1);
            const int xo = (xr + (p << 5)) * kXStr + xc;
            *(uint32_t*)&Xh[xo] = h0; *(uint32_t*)&Xh[xo + 2] = h1;
            *(uint32_t*)&Xl[xo] = l0; *(uint32_t*)&Xl[xo + 2] = l1;
            split4(ws[p], h0, h1, l0, l1);
            const int wo = (wr + (p << 3)) * kWStr + wc;
            *(uint32_t*)&Wh[wo] = h0; *(uint32_t*)&Wh[wo + 2] = h1;
            *(uint32_t*)&Wl[wo] = l0; *(uint32_t*)&Wl[wo + 2] = l1;
        }
        __syncthreads();

        if (k0 + 32 < kH) {
#pragma unroll
            for (int p = 0; p < 4; ++p) {
                xs[p] = *(const float4*)&X[(size_t)(m0 + xr + (p << 5)) * kH + k0 + 32 + xc];
                ws[p] = *(const float4*)&W[(size_t)(k0 + 32 + wr + (p << 3)) * kH + n0 + wc];
            }
        }

#pragma unroll
        for (int k16 = 0; k16 < 2; ++k16) {
            uint32_t afh[2][4], afl[2][4];
#pragma unroll
            for (int mi = 0; mi < 2; ++mi) {
                const int row = (wm << 5) + (mi << 4) + (lane & 15);
                const int col = (k16 << 4) + ((lane >> 4) << 3);
                ldsm_x4(afh[mi], smaddr(&Xh[row * kXStr + col]));
                ldsm_x4(afl[mi], smaddr(&Xl[row * kXStr + col]));
            }
#pragma unroll
            for (int jp = 0; jp < 4; ++jp) {
                const int brow = (k16 << 4) + (lane & 15);
                const int bcol = (wn << 6) + (jp << 4) + ((lane >> 4) << 3);
                uint32_t bh[4], bl[4];
                ldsm_x4t(bh, smaddr(&Wh[brow * kWStr + bcol]));
                ldsm_x4t(bl, smaddr(&Wl[brow * kWStr + bcol]));
#pragma unroll
                for (int mi = 0; mi < 2; ++mi) {
                    mma_bf16(acc[mi][2 * jp],     afh[mi], bh);
                    mma_bf16(acc[mi][2 * jp + 1], afh[mi], bh + 2);
                    mma_bf16(acc[mi][2 * jp],     afl[mi], bh);
                    mma_bf16(acc[mi][2 * jp + 1], afl[mi], bh + 2);
                    mma_bf16(acc[mi][2 * jp],     afh[mi], bl);
                    mma_bf16(acc[mi][2 * jp + 1], afh[mi], bl + 2);
                }
            }
        }
    }

    __nv_bfloat16* oh = (mode == 0) ? g_qhi : g_khi;
    __nv_bfloat16* ol = (mode == 0) ? g_qlo : g_klo;

#pragma unroll
    for (int jn = 0; jn < 8; ++jn) {
        const int n = n0 + (wn << 6) + (jn << 3) + ((lane & 3) << 1);
        float2 bv = *(const float2*)&bias[n];
#pragma unroll
        for (int mi = 0; mi < 2; ++mi) {
#pragma unroll
            for (int half = 0; half < 2; ++half) {
                const int m = m0 + (wm << 5) + (mi << 4) + (lane >> 2) + (half << 3);
                float v0 = acc[mi][jn][half * 2 + 0] + bv.x;
                float v1 = acc[mi][jn][half * 2 + 1] + bv.y;
                if (mode == 0) { v0 *= kScale; v1 *= kScale; }
                if (mode < 3) {
                    const int b_ = m >> 11;
                    const int s_ = m & (kS - 1);
                    const int h_ = n >> 6;
                    const int d_ = n & (kDK - 1);
                    size_t off = (((size_t)(b_ * kNH + h_)) * kS + s_) * kDK + d_;
                    if (mode < 2) {
                        __nv_bfloat162 hv = __floats2bfloat162_rn(v0, v1);
                        *(__nv_bfloat162*)&oh[off] = hv;
                        *(uint32_t*)&ol[off] = pack_bf16(v0 - __low2float(hv),
                                                         v1 - __high2float(hv));
                    } else {
                        __half2 hv = __floats2half2_rn(v0, v1);
                        *(__half2*)&g_vhi[off] = hv;
                        float h0f = __half2float(__low2half(hv));
                        float h1f = __half2float(__high2half(hv));
                        *(uint32_t*)&g_vlo[off] = pack_fp16(v0 - h0f, v1 - h1f);
                    }
                } else {
                    *(float2*)&Yout[(size_t)m * kH + n] = make_float2(v0, v1);
                }
            }
        }
    }
}

__global__ __launch_bounds__(256, 1) void qkv_gemm(
    const float* __restrict__ q, const float* __restrict__ k,
    const float* __restrict__ v,
    const float* __restrict__ Wq, const float* __restrict__ Wk,
    const float* __restrict__ Wv,
    const float* __restrict__ bq, const float* __restrict__ bk,
    const float* __restrict__ bv)
{
    const int mode = blockIdx.z;
    const float* X = (mode == 0) ? q : (mode == 1) ? k : v;
    const float* W = (mode == 0) ? Wq : (mode == 1) ? Wk : Wv;
    const float* B = (mode == 0) ? bq : (mode == 1) ? bk : bv;
    gemm_core(X, W, B, nullptr, mode);
}

__global__ __launch_bounds__(256, 1) void out_gemm(
    const float* __restrict__ Wo, const float* __restrict__ bo,
    float* __restrict__ out)
{
    gemm_core(g_ctx, Wo, bo, out, 3);
}

// ---------------------------------------------------------------------------
// Tensor-core flash attention (R7 frame) + R9: bias register prefetch.
// All 32 bias LDGs per warp per tile issued (streaming) BEFORE the cp.async
// wait + QK MMA block, consumed only at the exp step -> DRAM latency hidden.
// ---------------------------------------------------------------------------
constexpr int kQStr = 72;
constexpr int kTileE = 128 * kQStr;
constexpr int kStageE = 4 * kTileE;           // stage = Kh,Kl,Vh,Vl

__global__ __launch_bounds__(256, 1) void attn_kernel(const float* __restrict__ bias)
{
    extern __shared__ __nv_bfloat16 sm[];
    __nv_bfloat16* Qh = sm;
    __nv_bfloat16* Ql = Qh + kTileE;
    __nv_bfloat16* KV = Ql + kTileE;

    const int bh = blockIdx.y;
    const int q0 = blockIdx.x << 7;
    const int tid = threadIdx.x;
    const int lane = tid & 31, w = tid >> 5;

    const size_t hb = (size_t)bh * kS * kDK;
    const __nv_bfloat16* Kgh = g_khi + hb;
    const __nv_bfloat16* Kgl = g_klo + hb;
    const __half*        Vgh = g_vhi + hb;
    const __half*        Vgl = g_vlo + hb;
    const float* Bp = bias + (size_t)bh * kS * kS + (size_t)q0 * kS;

    const int r = tid >> 3, c8 = (tid & 7) << 3;

    {
        __nv_bfloat16* Kh = KV;
        __nv_bfloat16* Kl = Kh + kTileE;
        __nv_bfloat16* Vh = Kl + kTileE;
        __nv_bfloat16* Vl = Vh + kTileE;
#pragma unroll
        for (int u = 0; u < 4; ++u) {
            const int row = r + (u << 5);
            const size_t g = (size_t)row * kDK + c8;
            const int so = row * kQStr + c8;
            cp16(smaddr(&Kh[so]), &Kgh[g]);
            cp16(smaddr(&Kl[so]), &Kgl[g]);
            cp16(smaddr(&Vh[so]), &Vgh[g]);
            cp16(smaddr(&Vl[so]), &Vgl[g]);
        }
        cp_commit();
    }

    {
        const __nv_bfloat16* Qgh = g_qhi + hb;
        const __nv_bfloat16* Qgl = g_qlo + hb;
#pragma unroll
        for (int u = 0; u < 4; ++u) {
            const int row = r + (u << 5);
            *(uint4*)&Qh[row * kQStr + c8] =
                *(const uint4*)&Qgh[(size_t)(q0 + row) * kDK + c8];
            *(uint4*)&Ql[row * kQStr + c8] =
                *(const uint4*)&Qgl[(size_t)(q0 + row) * kDK + c8];
        }
    }
    __syncthreads();

    uint32_t qfh[4][4], qfl[4][4];
    {
        const int r0 = w << 4;
#pragma unroll
        for (int kc = 0; kc < 4; ++kc) {
            const int row = r0 + (lane & 15);
            const int col = (kc << 4) + ((lane >> 4) << 3);
            ldsm_x4(qfh[kc], smaddr(&Qh[row * kQStr + col]));
            ldsm_x4(qfl[kc], smaddr(&Ql[row * kQStr + col]));
        }
    }

    float O[8][4];
#pragma unroll
    for (int j = 0; j < 8; j++)
#pragma unroll
        for (int i = 0; i < 4; i++) O[j][i] = 0.f;
    float l0 = 0.f, l1 = 0.f;

    const int rq = lane >> 2;
    const int cq = (lane & 3) << 1;
    const int krow_off = (lane & 7) + ((lane >> 4) << 3);
    const int kcol_off = ((lane >> 3) & 1) << 3;
    const int vrow_off = lane & 15;
    const int vcol_off = (lane >> 4) << 3;

    // per-warp bias row base
    const float* Bw = Bp + (size_t)((w << 4) + rq) * kS + cq;

    for (int t = 0; t < kS / 128; ++t) {
        const int k0 = t << 7;

        // ---- bias register prefetch for THIS tile (streaming loads, issued
        //      before the KV wait and the whole QK MMA block) ----
        float br[16][4];
#pragma unroll
        for (int jp = 0; jp < 8; ++jp) {
            const float* bp = Bw + k0 + (jp << 4);
            float2 bA0 = __ldcs((const float2*)bp);
            float2 bB0 = __ldcs((const float2*)(bp + 8 * (size_t)kS));
            float2 bA1 = __ldcs((const float2*)(bp + 8));
            float2 bB1 = __ldcs((const float2*)(bp + 8 * (size_t)kS + 8));
            br[2 * jp][0] = bA0.x; br[2 * jp][1] = bA0.y;
            br[2 * jp][2] = bB0.x; br[2 * jp][3] = bB0.y;
            br[2 * jp + 1][0] = bA1.x; br[2 * jp + 1][1] = bA1.y;
            br[2 * jp + 1][2] = bB1.x; br[2 * jp + 1][3] = bB1.y;
        }

        if (t + 1 < kS / 128) {
            __nv_bfloat16* s = KV + ((t + 1) & 1) * kStageE;
            __nv_bfloat16* Kh = s;
            __nv_bfloat16* Kl = Kh + kTileE;
            __nv_bfloat16* Vh = Kl + kTileE;
            __nv_bfloat16* Vl = Vh + kTileE;
            const int k0n = (t + 1) << 7;
#pragma unroll
            for (int u = 0; u < 4; ++u) {
                const int row = r + (u << 5);
                const size_t g = (size_t)(k0n + row) * kDK + c8;
                const int so = row * kQStr + c8;
                cp16(smaddr(&Kh[so]), &Kgh[g]);
                cp16(smaddr(&Kl[so]), &Kgl[g]);
                cp16(smaddr(&Vh[so]), &Vgh[g]);
                cp16(smaddr(&Vl[so]), &Vgl[g]);
            }
            cp_commit();
            cp_wait<1>();
        } else {
            cp_wait<0>();
        }
        __syncthreads();

        __nv_bfloat16* s = KV + (t & 1) * kStageE;
        const __nv_bfloat16* Kh = s;
        const __nv_bfloat16* Kl = Kh + kTileE;
        const __nv_bfloat16* Vh = Kl + kTileE;
        const __nv_bfloat16* Vl = Vh + kTileE;

        // scores (bf16 3-MMA split) — bias loads in flight during this block
        float acc[16][4];
#pragma unroll
        for (int jp = 0; jp < 8; ++jp) {
            float* a0 = acc[2 * jp];
            float* a1 = acc[2 * jp + 1];
            a0[0] = a0[1] = a0[2] = a0[3] = 0.f;
            a1[0] = a1[1] = a1[2] = a1[3] = 0.f;
            const int rowb = (jp << 4) + krow_off;
#pragma unroll
            for (int kc = 0; kc < 4; ++kc) {
                const int col = (kc << 4) + kcol_off;
                uint32_t kb[4], kbl[4];
                ldsm_x4(kb, smaddr(&Kh[rowb * kQStr + col]));
                mma_bf16(a0, qfh[kc], kb);
                mma_bf16(a1, qfh[kc], kb + 2);
                mma_bf16(a0, qfl[kc], kb);
                mma_bf16(a1, qfl[kc], kb + 2);
                ldsm_x4(kbl, smaddr(&Kl[rowb * kQStr + col]));
                mma_bf16(a0, qfh[kc], kbl);
                mma_bf16(a1, qfh[kc], kbl + 2);
            }
        }

        // no-max softmax: p = exp(score + bias)
        uint32_t Ph[8][4];
#pragma unroll
        for (int j = 0; j < 16; ++j) {
            float p0 = __expf(acc[j][0] + br[j][0]);
            float p1 = __expf(acc[j][1] + br[j][1]);
            float p2 = __expf(acc[j][2] + br[j][2]);
            float p3 = __expf(acc[j][3] + br[j][3]);
            l0 += p0 + p1;
            l1 += p2 + p3;
            const int kc = j >> 1, bofs = (j & 1) << 1;
            Ph[kc][bofs]     = pack_fp16(p0, p1);
            Ph[kc][bofs + 1] = pack_fp16(p2, p3);
        }

        // O += P @ (Vhi + Vlo)  (fp16 MMAs)
#pragma unroll
        for (int jp = 0; jp < 4; ++jp) {
            float* o0 = O[2 * jp];
            float* o1 = O[2 * jp + 1];
            const int colb = (jp << 4) + vcol_off;
#pragma unroll
            for (int kc = 0; kc < 8; ++kc) {
                const int rowv = (kc << 4) + vrow_off;
                uint32_t vb[4], vbl[4];
                ldsm_x4t(vb, smaddr(&Vh[rowv * kQStr + colb]));
                mma_fp16(o0, Ph[kc], vb);
                mma_fp16(o1, Ph[kc], vb + 2);
                ldsm_x4t(vbl, smaddr(&Vl[rowv * kQStr + colb]));
                mma_fp16(o0, Ph[kc], vbl);
                mma_fp16(o1, Ph[kc], vbl + 2);
            }
        }
        __syncthreads();
    }

    // epilogue
    l0 += __shfl_xor_sync(0xffffffffu, l0, 1);
    l0 += __shfl_xor_sync(0xffffffffu, l0, 2);
    l1 += __shfl_xor_sync(0xffffffffu, l1, 1);
    l1 += __shfl_xor_sync(0xffffffffu, l1, 2);
    const float inv0 = 1.f / l0, inv1 = 1.f / l1;

    const int b_ = bh >> 3, h_ = bh & 7;
    const int grow = q0 + (w << 4) + rq;
    float* cp = g_ctx + ((size_t)b_ * kS + grow) * kH + h_ * kDK + cq;
#pragma unroll
    for (int jn = 0; jn < 8; ++jn) {
        *(float2*)(cp + (jn << 3)) =
            make_float2(O[jn][0] * inv0, O[jn][1] * inv0);
        *(float2*)(cp + (jn << 3) + 8 * kH) =
            make_float2(O[jn][2] * inv1, O[jn][3] * inv1);
    }
}

// ---------------------------------------------------------------------------
extern "C" void kernel_launch(void* const* d_in, const int* in_sizes, int n_in,
                              void* d_out, int out_size)
{
    const float* q  = (const float*)d_in[0];
    const float* k  = (const float*)d_in[1];
    const float* v  = (const float*)d_in[2];
    const float* ab = (const float*)d_in[3];
    const float* Wq = (const float*)d_in[4];
    const float* bq = (const float*)d_in[5];
    const float* Wk = (const float*)d_in[6];
    const float* bk = (const float*)d_in[7];
    const float* Wv = (const float*)d_in[8];
    const float* bv = (const float*)d_in[9];
    const float* Wo = (const float*)d_in[10];
    const float* bo = (const float*)d_in[11];
    float* out = (float*)d_out;

    const int attn_smem = (2 * kTileE + 2 * kStageE) * 2;   // 184320 bytes
    cudaFuncSetAttribute(attn_kernel,
                         cudaFuncAttributeMaxDynamicSharedMemorySize, attn_smem);

    dim3 blk(256);
    qkv_gemm<<<dim3(kH / 128, kM / 128, 3), blk>>>(q, k, v, Wq, Wk, Wv, bq, bk, bv);
    attn_kernel<<<dim3(kS / 128, kB * kNH), blk, attn_smem>>>(ab);
    out_gemm<<<dim3(kH / 128, kM / 128), blk>>>(Wo, bo, out);
}

// round 11
// speedup vs baseline: 1.1819x; 1.0726x over previous
#include <cuda_runtime.h>
#include <cuda_bf16.h>
#include <cuda_fp16.h>
#include <cstdint>

// Problem constants
constexpr int kB  = 2;
constexpr int kS  = 2048;
constexpr int kH  = 512;
constexpr int kNH = 8;
constexpr int kDK = 64;
constexpr int kM  = kB * kS;       // 4096
constexpr float kScale = 0.125f;   // 1/sqrt(64)

constexpr int kHE = kB * kNH * kS * kDK;  // elems per head tensor (2M)

// Scratch (device globals; no allocations allowed)
__device__ __half g_qhi[kHE], g_qlo[kHE];   // Q fp16 hi/lo (pre-scaled)
__device__ __half g_khi[kHE];               // K fp16 single
__device__ __half g_vhi[kHE], g_vlo[kHE];   // V fp16 hi/lo
__device__ float  g_ctx[kM * kH];           // [B*S, H]

// ---------------------------------------------------------------------------
// MMA / async-copy helpers
// ---------------------------------------------------------------------------
__device__ __forceinline__ uint32_t smaddr(const void* p) {
    return (uint32_t)__cvta_generic_to_shared(p);
}
__device__ __forceinline__ void ldsm_x4(uint32_t* r, uint32_t a) {
    asm volatile("ldmatrix.sync.aligned.m8n8.x4.shared.b16 {%0,%1,%2,%3},[%4];"
        : "=r"(r[0]), "=r"(r[1]), "=r"(r[2]), "=r"(r[3]) : "r"(a));
}
__device__ __forceinline__ void ldsm_x4t(uint32_t* r, uint32_t a) {
    asm volatile("ldmatrix.sync.aligned.m8n8.x4.trans.shared.b16 {%0,%1,%2,%3},[%4];"
        : "=r"(r[0]), "=r"(r[1]), "=r"(r[2]), "=r"(r[3]) : "r"(a));
}
__device__ __forceinline__ void ldsm_x2t(uint32_t* r, uint32_t a) {
    asm volatile("ldmatrix.sync.aligned.m8n8.x2.trans.shared.b16 {%0,%1},[%2];"
        : "=r"(r[0]), "=r"(r[1]) : "r"(a));
}
__device__ __forceinline__ void mma_bf16(float* c, const uint32_t* a,
                                         const uint32_t* b) {
    asm volatile(
        "mma.sync.aligned.m16n8k16.row.col.f32.bf16.bf16.f32 "
        "{%0,%1,%2,%3},{%4,%5,%6,%7},{%8,%9},{%0,%1,%2,%3};"
        : "+f"(c[0]), "+f"(c[1]), "+f"(c[2]), "+f"(c[3])
        : "r"(a[0]), "r"(a[1]), "r"(a[2]), "r"(a[3]), "r"(b[0]), "r"(b[1]));
}
__device__ __forceinline__ void mma_fp16(float* c, const uint32_t* a,
                                         const uint32_t* b) {
    asm volatile(
        "mma.sync.aligned.m16n8k16.row.col.f32.f16.f16.f32 "
        "{%0,%1,%2,%3},{%4,%5,%6,%7},{%8,%9},{%0,%1,%2,%3};"
        : "+f"(c[0]), "+f"(c[1]), "+f"(c[2]), "+f"(c[3])
        : "r"(a[0]), "r"(a[1]), "r"(a[2]), "r"(a[3]), "r"(b[0]), "r"(b[1]));
}
__device__ __forceinline__ uint32_t pack_bf16(float x, float y) {
    __nv_bfloat162 h = __floats2bfloat162_rn(x, y);
    return *reinterpret_cast<uint32_t*>(&h);
}
__device__ __forceinline__ uint32_t pack_fp16(float x, float y) {
    __half2 h = __floats2half2_rn(x, y);
    return *reinterpret_cast<uint32_t*>(&h);
}
__device__ __forceinline__ void split4(float4 v, uint32_t& h0, uint32_t& h1,
                                       uint32_t& l0, uint32_t& l1) {
    __nv_bfloat162 a = __floats2bfloat162_rn(v.x, v.y);
    __nv_bfloat162 b = __floats2bfloat162_rn(v.z, v.w);
    h0 = *reinterpret_cast<uint32_t*>(&a);
    h1 = *reinterpret_cast<uint32_t*>(&b);
    l0 = pack_bf16(v.x - __low2float(a), v.y - __high2float(a));
    l1 = pack_bf16(v.z - __low2float(b), v.w - __high2float(b));
}
__device__ __forceinline__ void cp16(uint32_t dst, const void* src) {
    asm volatile("cp.async.cg.shared.global [%0],[%1],16;"
        :: "r"(dst), "l"(src));
}
__device__ __forceinline__ void cp_commit() {
    asm volatile("cp.async.commit_group;");
}
template <int N>
__device__ __forceinline__ void cp_wait() {
    asm volatile("cp.async.wait_group %0;" :: "n"(N));
}

// ---------------------------------------------------------------------------
// Tensor-core GEMM (R7/R9 proven version; bf16 3-MMA internal).
// mode 0: Q out fp16 hi/lo scaled. mode 1: K out fp16 single.
// mode 2: V out fp16 hi/lo. mode 3: fp32 out.
// ---------------------------------------------------------------------------
constexpr int kXStr = 40;
constexpr int kWStr = 136;

__device__ __forceinline__ void gemm_core(
    const float* __restrict__ X, const float* __restrict__ W,
    const float* __restrict__ bias, float* __restrict__ Yout, int mode)
{
    __shared__ __nv_bfloat16 Xh[128 * kXStr], Xl[128 * kXStr];
    __shared__ __nv_bfloat16 Wh[32 * kWStr],  Wl[32 * kWStr];

    const int tid  = threadIdx.x;
    const int lane = tid & 31, w = tid >> 5;
    const int wm = w >> 1, wn = w & 1;
    const int m0 = blockIdx.y << 7, n0 = blockIdx.x << 7;

    float acc[2][8][4];
#pragma unroll
    for (int mi = 0; mi < 2; ++mi)
#pragma unroll
        for (int jn = 0; jn < 8; ++jn)
#pragma unroll
            for (int i = 0; i < 4; ++i) acc[mi][jn][i] = 0.f;

    const int xr = tid >> 3, xc = (tid & 7) << 2;
    const int wr = tid >> 5, wc = (tid & 31) << 2;

    float4 xs[4], ws[4];
#pragma unroll
    for (int p = 0; p < 4; ++p) {
        xs[p] = *(const float4*)&X[(size_t)(m0 + xr + (p << 5)) * kH + xc];
        ws[p] = *(const float4*)&W[(size_t)(wr + (p << 3)) * kH + n0 + wc];
    }

    for (int k0 = 0; k0 < kH; k0 += 32) {
        __syncthreads();
#pragma unroll
        for (int p = 0; p < 4; ++p) {
            uint32_t h0, h1, l0, l1;
            split4(xs[p], h0, h1, l0, l1);
            const int xo = (xr + (p << 5)) * kXStr + xc;
            *(uint32_t*)&Xh[xo] = h0; *(uint32_t*)&Xh[xo + 2] = h1;
            *(uint32_t*)&Xl[xo] = l0; *(uint32_t*)&Xl[xo + 2] = l1;
            split4(ws[p], h0, h1, l0, l1);
            const int wo = (wr + (p << 3)) * kWStr + wc;
            *(uint32_t*)&Wh[wo] = h0; *(uint32_t*)&Wh[wo + 2] = h1;
            *(uint32_t*)&Wl[wo] = l0; *(uint32_t*)&Wl[wo + 2] = l1;
        }
        __syncthreads();

        if (k0 + 32 < kH) {
#pragma unroll
            for (int p = 0; p < 4; ++p) {
                xs[p] = *(const float4*)&X[(size_t)(m0 + xr + (p << 5)) * kH + k0 + 32 + xc];
                ws[p] = *(const float4*)&W[(size_t)(k0 + 32 + wr + (p << 3)) * kH + n0 + wc];
            }
        }

#pragma unroll
        for (int k16 = 0; k16 < 2; ++k16) {
            uint32_t afh[2][4], afl[2][4];
#pragma unroll
            for (int mi = 0; mi < 2; ++mi) {
                const int row = (wm << 5) + (mi << 4) + (lane & 15);
                const int col = (k16 << 4) + ((lane >> 4) << 3);
                ldsm_x4(afh[mi], smaddr(&Xh[row * kXStr + col]));
                ldsm_x4(afl[mi], smaddr(&Xl[row * kXStr + col]));
            }
#pragma unroll
            for (int jp = 0; jp < 4; ++jp) {
                const int brow = (k16 << 4) + (lane & 15);
                const int bcol = (wn << 6) + (jp << 4) + ((lane >> 4) << 3);
                uint32_t bh[4], bl[4];
                ldsm_x4t(bh, smaddr(&Wh[brow * kWStr + bcol]));
                ldsm_x4t(bl, smaddr(&Wl[brow * kWStr + bcol]));
#pragma unroll
                for (int mi = 0; mi < 2; ++mi) {
                    mma_bf16(acc[mi][2 * jp],     afh[mi], bh);
                    mma_bf16(acc[mi][2 * jp + 1], afh[mi], bh + 2);
                    mma_bf16(acc[mi][2 * jp],     afl[mi], bh);
                    mma_bf16(acc[mi][2 * jp + 1], afl[mi], bh + 2);
                    mma_bf16(acc[mi][2 * jp],     afh[mi], bl);
                    mma_bf16(acc[mi][2 * jp + 1], afh[mi], bl + 2);
                }
            }
        }
    }

#pragma unroll
    for (int jn = 0; jn < 8; ++jn) {
        const int n = n0 + (wn << 6) + (jn << 3) + ((lane & 3) << 1);
        float2 bv = *(const float2*)&bias[n];
#pragma unroll
        for (int mi = 0; mi < 2; ++mi) {
#pragma unroll
            for (int half = 0; half < 2; ++half) {
                const int m = m0 + (wm << 5) + (mi << 4) + (lane >> 2) + (half << 3);
                float v0 = acc[mi][jn][half * 2 + 0] + bv.x;
                float v1 = acc[mi][jn][half * 2 + 1] + bv.y;
                if (mode == 0) { v0 *= kScale; v1 *= kScale; }
                if (mode < 3) {
                    const int b_ = m >> 11;
                    const int s_ = m & (kS - 1);
                    const int h_ = n >> 6;
                    const int d_ = n & (kDK - 1);
                    size_t off = (((size_t)(b_ * kNH + h_)) * kS + s_) * kDK + d_;
                    __half2 hv = __floats2half2_rn(v0, v1);
                    if (mode == 0) {
                        *(__half2*)&g_qhi[off] = hv;
                        float h0f = __half2float(__low2half(hv));
                        float h1f = __half2float(__high2half(hv));
                        *(uint32_t*)&g_qlo[off] = pack_fp16(v0 - h0f, v1 - h1f);
                    } else if (mode == 1) {
                        *(__half2*)&g_khi[off] = hv;
                    } else {
                        *(__half2*)&g_vhi[off] = hv;
                        float h0f = __half2float(__low2half(hv));
                        float h1f = __half2float(__high2half(hv));
                        *(uint32_t*)&g_vlo[off] = pack_fp16(v0 - h0f, v1 - h1f);
                    }
                } else {
                    *(float2*)&Yout[(size_t)m * kH + n] = make_float2(v0, v1);
                }
            }
        }
    }
}

__global__ __launch_bounds__(256, 1) void qkv_gemm(
    const float* __restrict__ q, const float* __restrict__ k,
    const float* __restrict__ v,
    const float* __restrict__ Wq, const float* __restrict__ Wk,
    const float* __restrict__ Wv,
    const float* __restrict__ bq, const float* __restrict__ bk,
    const float* __restrict__ bv)
{
    const int mode = blockIdx.z;
    const float* X = (mode == 0) ? q : (mode == 1) ? k : v;
    const float* W = (mode == 0) ? Wq : (mode == 1) ? Wk : Wv;
    const float* B = (mode == 0) ? bq : (mode == 1) ? bk : bv;
    gemm_core(X, W, B, nullptr, mode);
}

__global__ __launch_bounds__(256, 1) void out_gemm(
    const float* __restrict__ Wo, const float* __restrict__ bo,
    float* __restrict__ out)
{
    gemm_core(g_ctx, Wo, bo, out, 3);
}

// ---------------------------------------------------------------------------
// Tensor-core flash attention. R11:
//  - QK in fp16: Q hi/lo x K single -> 2 MMAs (was bf16 3-MMA)
//  - PV in fp16: P single x V hi/lo -> 2 MMAs (R7, validated)
//  - no-max softmax + bias register prefetch (R5/R9, validated)
// stage = Kh, Vh, Vl (3 fp16 tiles); smem = (2 + 6) * 18432 = 147456 B.
// ---------------------------------------------------------------------------
constexpr int kQStr = 72;
constexpr int kTileE = 128 * kQStr;
constexpr int kStageE = 3 * kTileE;           // stage = Kh,Vh,Vl

__global__ __launch_bounds__(256, 1) void attn_kernel(const float* __restrict__ bias)
{
    extern __shared__ __half sm[];
    __half* Qh = sm;
    __half* Ql = Qh + kTileE;
    __half* KV = Ql + kTileE;

    const int bh = blockIdx.y;
    const int q0 = blockIdx.x << 7;
    const int tid = threadIdx.x;
    const int lane = tid & 31, w = tid >> 5;

    const size_t hb = (size_t)bh * kS * kDK;
    const __half* Kgh = g_khi + hb;
    const __half* Vgh = g_vhi + hb;
    const __half* Vgl = g_vlo + hb;
    const float* Bp = bias + (size_t)bh * kS * kS + (size_t)q0 * kS;

    const int r = tid >> 3, c8 = (tid & 7) << 3;

    // stage 0 <- tile 0 (Kh, Vh, Vl)
    {
        __half* Kh = KV;
        __half* Vh = Kh + kTileE;
        __half* Vl = Vh + kTileE;
#pragma unroll
        for (int u = 0; u < 4; ++u) {
            const int row = r + (u << 5);
            const size_t g = (size_t)row * kDK + c8;
            const int so = row * kQStr + c8;
            cp16(smaddr(&Kh[so]), &Kgh[g]);
            cp16(smaddr(&Vh[so]), &Vgh[g]);
            cp16(smaddr(&Vl[so]), &Vgl[g]);
        }
        cp_commit();
    }

    // Load Q tile (fp16 hi/lo)
    {
        const __half* Qgh = g_qhi + hb;
        const __half* Qgl = g_qlo + hb;
#pragma unroll
        for (int u = 0; u < 4; ++u) {
            const int row = r + (u << 5);
            *(uint4*)&Qh[row * kQStr + c8] =
                *(const uint4*)&Qgh[(size_t)(q0 + row) * kDK + c8];
            *(uint4*)&Ql[row * kQStr + c8] =
                *(const uint4*)&Qgl[(size_t)(q0 + row) * kDK + c8];
        }
    }
    __syncthreads();

    // Q fragments (resident)
    uint32_t qfh[4][4], qfl[4][4];
    {
        const int r0 = w << 4;
#pragma unroll
        for (int kc = 0; kc < 4; ++kc) {
            const int row = r0 + (lane & 15);
            const int col = (kc << 4) + ((lane >> 4) << 3);
            ldsm_x4(qfh[kc], smaddr(&Qh[row * kQStr + col]));
            ldsm_x4(qfl[kc], smaddr(&Ql[row * kQStr + col]));
        }
    }

    float O[8][4];
#pragma unroll
    for (int j = 0; j < 8; j++)
#pragma unroll
        for (int i = 0; i < 4; i++) O[j][i] = 0.f;
    float l0 = 0.f, l1 = 0.f;

    const int rq = lane >> 2;
    const int cq = (lane & 3) << 1;
    const int krow_off = (lane & 7) + ((lane >> 4) << 3);
    const int kcol_off = ((lane >> 3) & 1) << 3;
    const int vrow_off = lane & 15;
    const int vcol_off = (lane >> 4) << 3;

    const float* Bw = Bp + (size_t)((w << 4) + rq) * kS + cq;

    for (int t = 0; t < kS / 128; ++t) {
        const int k0 = t << 7;

        // bias register prefetch (streaming; consumed at exp step)
        float br[16][4];
#pragma unroll
        for (int jp = 0; jp < 8; ++jp) {
            const float* bp = Bw + k0 + (jp << 4);
            float2 bA0 = __ldcs((const float2*)bp);
            float2 bB0 = __ldcs((const float2*)(bp + 8 * (size_t)kS));
            float2 bA1 = __ldcs((const float2*)(bp + 8));
            float2 bB1 = __ldcs((const float2*)(bp + 8 * (size_t)kS + 8));
            br[2 * jp][0] = bA0.x; br[2 * jp][1] = bA0.y;
            br[2 * jp][2] = bB0.x; br[2 * jp][3] = bB0.y;
            br[2 * jp + 1][0] = bA1.x; br[2 * jp + 1][1] = bA1.y;
            br[2 * jp + 1][2] = bB1.x; br[2 * jp + 1][3] = bB1.y;
        }

        if (t + 1 < kS / 128) {
            __half* s = KV + ((t + 1) & 1) * kStageE;
            __half* Kh = s;
            __half* Vh = Kh + kTileE;
            __half* Vl = Vh + kTileE;
            const int k0n = (t + 1) << 7;
#pragma unroll
            for (int u = 0; u < 4; ++u) {
                const int row = r + (u << 5);
                const size_t g = (size_t)(k0n + row) * kDK + c8;
                const int so = row * kQStr + c8;
                cp16(smaddr(&Kh[so]), &Kgh[g]);
                cp16(smaddr(&Vh[so]), &Vgh[g]);
                cp16(smaddr(&Vl[so]), &Vgl[g]);
            }
            cp_commit();
            cp_wait<1>();
        } else {
            cp_wait<0>();
        }
        __syncthreads();

        __half* s = KV + (t & 1) * kStageE;
        const __half* Kh = s;
        const __half* Vh = Kh + kTileE;
        const __half* Vl = Vh + kTileE;

        // scores: fp16 2-MMA (Qhi*K + Qlo*K)
        float acc[16][4];
#pragma unroll
        for (int jp = 0; jp < 8; ++jp) {
            float* a0 = acc[2 * jp];
            float* a1 = acc[2 * jp + 1];
            a0[0] = a0[1] = a0[2] = a0[3] = 0.f;
            a1[0] = a1[1] = a1[2] = a1[3] = 0.f;
            const int rowb = (jp << 4) + krow_off;
#pragma unroll
            for (int kc = 0; kc < 4; ++kc) {
                const int col = (kc << 4) + kcol_off;
                uint32_t kb[4];
                ldsm_x4(kb, smaddr(&Kh[rowb * kQStr + col]));
                mma_fp16(a0, qfh[kc], kb);
                mma_fp16(a1, qfh[kc], kb + 2);
                mma_fp16(a0, qfl[kc], kb);
                mma_fp16(a1, qfl[kc], kb + 2);
            }
        }

        // no-max softmax: p = exp(score + bias), fp16 P fragments
        uint32_t Ph[8][4];
#pragma unroll
        for (int j = 0; j < 16; ++j) {
            float p0 = __expf(acc[j][0] + br[j][0]);
            float p1 = __expf(acc[j][1] + br[j][1]);
            float p2 = __expf(acc[j][2] + br[j][2]);
            float p3 = __expf(acc[j][3] + br[j][3]);
            l0 += p0 + p1;
            l1 += p2 + p3;
            const int kc = j >> 1, bofs = (j & 1) << 1;
            Ph[kc][bofs]     = pack_fp16(p0, p1);
            Ph[kc][bofs + 1] = pack_fp16(p2, p3);
        }

        // O += P @ (Vhi + Vlo)  (fp16 MMAs)
#pragma unroll
        for (int jp = 0; jp < 4; ++jp) {
            float* o0 = O[2 * jp];
            float* o1 = O[2 * jp + 1];
            const int colb = (jp << 4) + vcol_off;
#pragma unroll
            for (int kc = 0; kc < 8; ++kc) {
                const int rowv = (kc << 4) + vrow_off;
                uint32_t vb[4], vbl[4];
                ldsm_x4t(vb, smaddr(&Vh[rowv * kQStr + colb]));
                mma_fp16(o0, Ph[kc], vb);
                mma_fp16(o1, Ph[kc], vb + 2);
                ldsm_x4t(vbl, smaddr(&Vl[rowv * kQStr + colb]));
                mma_fp16(o0, Ph[kc], vbl);
                mma_fp16(o1, Ph[kc], vbl + 2);
            }
        }
        __syncthreads();
    }

    // epilogue
    l0 += __shfl_xor_sync(0xffffffffu, l0, 1);
    l0 += __shfl_xor_sync(0xffffffffu, l0, 2);
    l1 += __shfl_xor_sync(0xffffffffu, l1, 1);
    l1 += __shfl_xor_sync(0xffffffffu, l1, 2);
    const float inv0 = 1.f / l0, inv1 = 1.f / l1;

    const int b_ = bh >> 3, h_ = bh & 7;
    const int grow = q0 + (w << 4) + rq;
    float* cp = g_ctx + ((size_t)b_ * kS + grow) * kH + h_ * kDK + cq;
#pragma unroll
    for (int jn = 0; jn < 8; ++jn) {
        *(float2*)(cp + (jn << 3)) =
            make_float2(O[jn][0] * inv0, O[jn][1] * inv0);
        *(float2*)(cp + (jn << 3) + 8 * kH) =
            make_float2(O[jn][2] * inv1, O[jn][3] * inv1);
    }
}

// ---------------------------------------------------------------------------
extern "C" void kernel_launch(void* const* d_in, const int* in_sizes, int n_in,
                              void* d_out, int out_size)
{
    const float* q  = (const float*)d_in[0];
    const float* k  = (const float*)d_in[1];
    const float* v  = (const float*)d_in[2];
    const float* ab = (const float*)d_in[3];
    const float* Wq = (const float*)d_in[4];
    const float* bq = (const float*)d_in[5];
    const float* Wk = (const float*)d_in[6];
    const float* bk = (const float*)d_in[7];
    const float* Wv = (const float*)d_in[8];
    const float* bv = (const float*)d_in[9];
    const float* Wo = (const float*)d_in[10];
    const float* bo = (const float*)d_in[11];
    float* out = (float*)d_out;

    const int attn_smem = (2 * kTileE + 2 * kStageE) * 2;   // 147456 bytes
    cudaFuncSetAttribute(attn_kernel,
                         cudaFuncAttributeMaxDynamicSharedMemorySize, attn_smem);

    dim3 blk(256);
    qkv_gemm<<<dim3(kH / 128, kM / 128, 3), blk>>>(q, k, v, Wq, Wk, Wv, bq, bk, bv);
    attn_kernel<<<dim3(kS / 128, kB * kNH), blk, attn_smem>>>(ab);
    out_gemm<<<dim3(kH / 128, kM / 128), blk>>>(Wo, bo, out);
}

// round 12
// speedup vs baseline: 1.3932x; 1.1787x over previous
#include <cuda_runtime.h>
#include <cuda_bf16.h>
#include <cuda_fp16.h>
#include <cstdint>

// Problem constants
constexpr int kB  = 2;
constexpr int kS  = 2048;
constexpr int kH  = 512;
constexpr int kNH = 8;
constexpr int kDK = 64;
constexpr int kM  = kB * kS;       // 4096
constexpr float kScale = 0.125f;   // 1/sqrt(64)

constexpr int kHE = kB * kNH * kS * kDK;  // elems per head tensor (2M)

// Scratch (device globals; no allocations allowed)
__device__ __half g_qhi[kHE];               // Q fp16 single (pre-scaled)
__device__ __half g_khi[kHE];               // K fp16 single
__device__ __half g_vhi[kHE];               // V fp16 single
__device__ float  g_ctx[kM * kH];           // [B*S, H]

// ---------------------------------------------------------------------------
// MMA / async-copy helpers
// ---------------------------------------------------------------------------
__device__ __forceinline__ uint32_t smaddr(const void* p) {
    return (uint32_t)__cvta_generic_to_shared(p);
}
__device__ __forceinline__ void ldsm_x4(uint32_t* r, uint32_t a) {
    asm volatile("ldmatrix.sync.aligned.m8n8.x4.shared.b16 {%0,%1,%2,%3},[%4];"
        : "=r"(r[0]), "=r"(r[1]), "=r"(r[2]), "=r"(r[3]) : "r"(a));
}
__device__ __forceinline__ void ldsm_x4t(uint32_t* r, uint32_t a) {
    asm volatile("ldmatrix.sync.aligned.m8n8.x4.trans.shared.b16 {%0,%1,%2,%3},[%4];"
        : "=r"(r[0]), "=r"(r[1]), "=r"(r[2]), "=r"(r[3]) : "r"(a));
}
__device__ __forceinline__ void mma_bf16(float* c, const uint32_t* a,
                                         const uint32_t* b) {
    asm volatile(
        "mma.sync.aligned.m16n8k16.row.col.f32.bf16.bf16.f32 "
        "{%0,%1,%2,%3},{%4,%5,%6,%7},{%8,%9},{%0,%1,%2,%3};"
        : "+f"(c[0]), "+f"(c[1]), "+f"(c[2]), "+f"(c[3])
        : "r"(a[0]), "r"(a[1]), "r"(a[2]), "r"(a[3]), "r"(b[0]), "r"(b[1]));
}
__device__ __forceinline__ void mma_fp16(float* c, const uint32_t* a,
                                         const uint32_t* b) {
    asm volatile(
        "mma.sync.aligned.m16n8k16.row.col.f32.f16.f16.f32 "
        "{%0,%1,%2,%3},{%4,%5,%6,%7},{%8,%9},{%0,%1,%2,%3};"
        : "+f"(c[0]), "+f"(c[1]), "+f"(c[2]), "+f"(c[3])
        : "r"(a[0]), "r"(a[1]), "r"(a[2]), "r"(a[3]), "r"(b[0]), "r"(b[1]));
}
__device__ __forceinline__ uint32_t pack_bf16(float x, float y) {
    __nv_bfloat162 h = __floats2bfloat162_rn(x, y);
    return *reinterpret_cast<uint32_t*>(&h);
}
__device__ __forceinline__ uint32_t pack_fp16(float x, float y) {
    __half2 h = __floats2half2_rn(x, y);
    return *reinterpret_cast<uint32_t*>(&h);
}
__device__ __forceinline__ void split4(float4 v, uint32_t& h0, uint32_t& h1,
                                       uint32_t& l0, uint32_t& l1) {
    __nv_bfloat162 a = __floats2bfloat162_rn(v.x, v.y);
    __nv_bfloat162 b = __floats2bfloat162_rn(v.z, v.w);
    h0 = *reinterpret_cast<uint32_t*>(&a);
    h1 = *reinterpret_cast<uint32_t*>(&b);
    l0 = pack_bf16(v.x - __low2float(a), v.y - __high2float(a));
    l1 = pack_bf16(v.z - __low2float(b), v.w - __high2float(b));
}
__device__ __forceinline__ void cp16(uint32_t dst, const void* src) {
    asm volatile("cp.async.cg.shared.global [%0],[%1],16;"
        :: "r"(dst), "l"(src));
}
__device__ __forceinline__ void cp_commit() {
    asm volatile("cp.async.commit_group;");
}
template <int N>
__device__ __forceinline__ void cp_wait() {
    asm volatile("cp.async.wait_group %0;" :: "n"(N));
}

// ---------------------------------------------------------------------------
// Tensor-core GEMM (R7/R9 proven frame; bf16 3-MMA internal).
// mode 0: Q out fp16 single, scaled. mode 1: K out fp16 single.
// mode 2: V out fp16 single. mode 3: fp32 out.
// ---------------------------------------------------------------------------
constexpr int kXStr = 40;
constexpr int kWStr = 136;

__device__ __forceinline__ void gemm_core(
    const float* __restrict__ X, const float* __restrict__ W,
    const float* __restrict__ bias, float* __restrict__ Yout, int mode)
{
    __shared__ __nv_bfloat16 Xh[128 * kXStr], Xl[128 * kXStr];
    __shared__ __nv_bfloat16 Wh[32 * kWStr],  Wl[32 * kWStr];

    const int tid  = threadIdx.x;
    const int lane = tid & 31, w = tid >> 5;
    const int wm = w >> 1, wn = w & 1;
    const int m0 = blockIdx.y << 7, n0 = blockIdx.x << 7;

    float acc[2][8][4];
#pragma unroll
    for (int mi = 0; mi < 2; ++mi)
#pragma unroll
        for (int jn = 0; jn < 8; ++jn)
#pragma unroll
            for (int i = 0; i < 4; ++i) acc[mi][jn][i] = 0.f;

    const int xr = tid >> 3, xc = (tid & 7) << 2;
    const int wr = tid >> 5, wc = (tid & 31) << 2;

    float4 xs[4], ws[4];
#pragma unroll
    for (int p = 0; p < 4; ++p) {
        xs[p] = *(const float4*)&X[(size_t)(m0 + xr + (p << 5)) * kH + xc];
        ws[p] = *(const float4*)&W[(size_t)(wr + (p << 3)) * kH + n0 + wc];
    }

    for (int k0 = 0; k0 < kH; k0 += 32) {
        __syncthreads();
#pragma unroll
        for (int p = 0; p < 4; ++p) {
            uint32_t h0, h1, l0, l1;
            split4(xs[p], h0, h1, l0, l1);
            const int xo = (xr + (p << 5)) * kXStr + xc;
            *(uint32_t*)&Xh[xo] = h0; *(uint32_t*)&Xh[xo + 2] = h1;
            *(uint32_t*)&Xl[xo] = l0; *(uint32_t*)&Xl[xo + 2] = l1;
            split4(ws[p], h0, h1, l0, l1);
            const int wo = (wr + (p << 3)) * kWStr + wc;
            *(uint32_t*)&Wh[wo] = h0; *(uint32_t*)&Wh[wo + 2] = h1;
            *(uint32_t*)&Wl[wo] = l0; *(uint32_t*)&Wl[wo + 2] = l1;
        }
        __syncthreads();

        if (k0 + 32 < kH) {
#pragma unroll
            for (int p = 0; p < 4; ++p) {
                xs[p] = *(const float4*)&X[(size_t)(m0 + xr + (p << 5)) * kH + k0 + 32 + xc];
                ws[p] = *(const float4*)&W[(size_t)(k0 + 32 + wr + (p << 3)) * kH + n0 + wc];
            }
        }

#pragma unroll
        for (int k16 = 0; k16 < 2; ++k16) {
            uint32_t afh[2][4], afl[2][4];
#pragma unroll
            for (int mi = 0; mi < 2; ++mi) {
                const int row = (wm << 5) + (mi << 4) + (lane & 15);
                const int col = (k16 << 4) + ((lane >> 4) << 3);
                ldsm_x4(afh[mi], smaddr(&Xh[row * kXStr + col]));
                ldsm_x4(afl[mi], smaddr(&Xl[row * kXStr + col]));
            }
#pragma unroll
            for (int jp = 0; jp < 4; ++jp) {
                const int brow = (k16 << 4) + (lane & 15);
                const int bcol = (wn << 6) + (jp << 4) + ((lane >> 4) << 3);
                uint32_t bh[4], bl[4];
                ldsm_x4t(bh, smaddr(&Wh[brow * kWStr + bcol]));
                ldsm_x4t(bl, smaddr(&Wl[brow * kWStr + bcol]));
#pragma unroll
                for (int mi = 0; mi < 2; ++mi) {
                    mma_bf16(acc[mi][2 * jp],     afh[mi], bh);
                    mma_bf16(acc[mi][2 * jp + 1], afh[mi], bh + 2);
                    mma_bf16(acc[mi][2 * jp],     afl[mi], bh);
                    mma_bf16(acc[mi][2 * jp + 1], afl[mi], bh + 2);
                    mma_bf16(acc[mi][2 * jp],     afh[mi], bl);
                    mma_bf16(acc[mi][2 * jp + 1], afh[mi], bl + 2);
                }
            }
        }
    }

#pragma unroll
    for (int jn = 0; jn < 8; ++jn) {
        const int n = n0 + (wn << 6) + (jn << 3) + ((lane & 3) << 1);
        float2 bv = *(const float2*)&bias[n];
#pragma unroll
        for (int mi = 0; mi < 2; ++mi) {
#pragma unroll
            for (int half = 0; half < 2; ++half) {
                const int m = m0 + (wm << 5) + (mi << 4) + (lane >> 2) + (half << 3);
                float v0 = acc[mi][jn][half * 2 + 0] + bv.x;
                float v1 = acc[mi][jn][half * 2 + 1] + bv.y;
                if (mode == 0) { v0 *= kScale; v1 *= kScale; }
                if (mode < 3) {
                    const int b_ = m >> 11;
                    const int s_ = m & (kS - 1);
                    const int h_ = n >> 6;
                    const int d_ = n & (kDK - 1);
                    size_t off = (((size_t)(b_ * kNH + h_)) * kS + s_) * kDK + d_;
                    __half2 hv = __floats2half2_rn(v0, v1);
                    __half* dst = (mode == 0) ? g_qhi : (mode == 1) ? g_khi : g_vhi;
                    *(__half2*)&dst[off] = hv;
                } else {
                    *(float2*)&Yout[(size_t)m * kH + n] = make_float2(v0, v1);
                }
            }
        }
    }
}

__global__ __launch_bounds__(256, 1) void qkv_gemm(
    const float* __restrict__ q, const float* __restrict__ k,
    const float* __restrict__ v,
    const float* __restrict__ Wq, const float* __restrict__ Wk,
    const float* __restrict__ Wv,
    const float* __restrict__ bq, const float* __restrict__ bk,
    const float* __restrict__ bv)
{
    const int mode = blockIdx.z;
    const float* X = (mode == 0) ? q : (mode == 1) ? k : v;
    const float* W = (mode == 0) ? Wq : (mode == 1) ? Wk : Wv;
    const float* B = (mode == 0) ? bq : (mode == 1) ? bk : bv;
    gemm_core(X, W, B, nullptr, mode);
}

__global__ __launch_bounds__(256, 1) void out_gemm(
    const float* __restrict__ Wo, const float* __restrict__ bo,
    float* __restrict__ out)
{
    gemm_core(g_ctx, Wo, bo, out, 3);
}

// ---------------------------------------------------------------------------
// Tensor-core flash attention. R12: all-fp16-single attention.
//  - QK: Q x K, 1 MMA per fragment pair (64 MMAs/warp/tile)
//  - PV: P x V, 1 MMA per fragment pair (64 MMAs/warp/tile)
//  - no-max softmax + bias register prefetch (validated)
// stage = Kh, Vh (2 fp16 tiles); smem = (1 + 4) * 18432 = 92160 B.
// ---------------------------------------------------------------------------
constexpr int kQStr = 72;
constexpr int kTileE = 128 * kQStr;
constexpr int kStageE = 2 * kTileE;           // stage = Kh,Vh

__global__ __launch_bounds__(256, 1) void attn_kernel(const float* __restrict__ bias)
{
    extern __shared__ __half sm[];
    __half* Qh = sm;
    __half* KV = Qh + kTileE;

    const int bh = blockIdx.y;
    const int q0 = blockIdx.x << 7;
    const int tid = threadIdx.x;
    const int lane = tid & 31, w = tid >> 5;

    const size_t hb = (size_t)bh * kS * kDK;
    const __half* Kgh = g_khi + hb;
    const __half* Vgh = g_vhi + hb;
    const float* Bp = bias + (size_t)bh * kS * kS + (size_t)q0 * kS;

    const int r = tid >> 3, c8 = (tid & 7) << 3;

    // stage 0 <- tile 0 (Kh, Vh)
    {
        __half* Kh = KV;
        __half* Vh = Kh + kTileE;
#pragma unroll
        for (int u = 0; u < 4; ++u) {
            const int row = r + (u << 5);
            const size_t g = (size_t)row * kDK + c8;
            const int so = row * kQStr + c8;
            cp16(smaddr(&Kh[so]), &Kgh[g]);
            cp16(smaddr(&Vh[so]), &Vgh[g]);
        }
        cp_commit();
    }

    // Load Q tile (fp16 single)
    {
        const __half* Qgh = g_qhi + hb;
#pragma unroll
        for (int u = 0; u < 4; ++u) {
            const int row = r + (u << 5);
            *(uint4*)&Qh[row * kQStr + c8] =
                *(const uint4*)&Qgh[(size_t)(q0 + row) * kDK + c8];
        }
    }
    __syncthreads();

    // Q fragments (resident)
    uint32_t qf[4][4];
    {
        const int r0 = w << 4;
#pragma unroll
        for (int kc = 0; kc < 4; ++kc) {
            const int row = r0 + (lane & 15);
            const int col = (kc << 4) + ((lane >> 4) << 3);
            ldsm_x4(qf[kc], smaddr(&Qh[row * kQStr + col]));
        }
    }

    float O[8][4];
#pragma unroll
    for (int j = 0; j < 8; j++)
#pragma unroll
        for (int i = 0; i < 4; i++) O[j][i] = 0.f;
    float l0 = 0.f, l1 = 0.f;

    const int rq = lane >> 2;
    const int cq = (lane & 3) << 1;
    const int krow_off = (lane & 7) + ((lane >> 4) << 3);
    const int kcol_off = ((lane >> 3) & 1) << 3;
    const int vrow_off = lane & 15;
    const int vcol_off = (lane >> 4) << 3;

    const float* Bw = Bp + (size_t)((w << 4) + rq) * kS + cq;

    for (int t = 0; t < kS / 128; ++t) {
        const int k0 = t << 7;

        // bias register prefetch (streaming; consumed at exp step)
        float br[16][4];
#pragma unroll
        for (int jp = 0; jp < 8; ++jp) {
            const float* bp = Bw + k0 + (jp << 4);
            float2 bA0 = __ldcs((const float2*)bp);
            float2 bB0 = __ldcs((const float2*)(bp + 8 * (size_t)kS));
            float2 bA1 = __ldcs((const float2*)(bp + 8));
            float2 bB1 = __ldcs((const float2*)(bp + 8 * (size_t)kS + 8));
            br[2 * jp][0] = bA0.x; br[2 * jp][1] = bA0.y;
            br[2 * jp][2] = bB0.x; br[2 * jp][3] = bB0.y;
            br[2 * jp + 1][0] = bA1.x; br[2 * jp + 1][1] = bA1.y;
            br[2 * jp + 1][2] = bB1.x; br[2 * jp + 1][3] = bB1.y;
        }

        if (t + 1 < kS / 128) {
            __half* s = KV + ((t + 1) & 1) * kStageE;
            __half* Kh = s;
            __half* Vh = Kh + kTileE;
            const int k0n = (t + 1) << 7;
#pragma unroll
            for (int u = 0; u < 4; ++u) {
                const int row = r + (u << 5);
                const size_t g = (size_t)(k0n + row) * kDK + c8;
                const int so = row * kQStr + c8;
                cp16(smaddr(&Kh[so]), &Kgh[g]);
                cp16(smaddr(&Vh[so]), &Vgh[g]);
            }
            cp_commit();
            cp_wait<1>();
        } else {
            cp_wait<0>();
        }
        __syncthreads();

        __half* s = KV + (t & 1) * kStageE;
        const __half* Kh = s;
        const __half* Vh = Kh + kTileE;

        // scores: fp16 single MMA
        float acc[16][4];
#pragma unroll
        for (int jp = 0; jp < 8; ++jp) {
            float* a0 = acc[2 * jp];
            float* a1 = acc[2 * jp + 1];
            a0[0] = a0[1] = a0[2] = a0[3] = 0.f;
            a1[0] = a1[1] = a1[2] = a1[3] = 0.f;
            const int rowb = (jp << 4) + krow_off;
#pragma unroll
            for (int kc = 0; kc < 4; ++kc) {
                const int col = (kc << 4) + kcol_off;
                uint32_t kb[4];
                ldsm_x4(kb, smaddr(&Kh[rowb * kQStr + col]));
                mma_fp16(a0, qf[kc], kb);
                mma_fp16(a1, qf[kc], kb + 2);
            }
        }

        // no-max softmax: p = exp(score + bias), fp16 P fragments
        uint32_t Ph[8][4];
#pragma unroll
        for (int j = 0; j < 16; ++j) {
            float p0 = __expf(acc[j][0] + br[j][0]);
            float p1 = __expf(acc[j][1] + br[j][1]);
            float p2 = __expf(acc[j][2] + br[j][2]);
            float p3 = __expf(acc[j][3] + br[j][3]);
            l0 += p0 + p1;
            l1 += p2 + p3;
            const int kc = j >> 1, bofs = (j & 1) << 1;
            Ph[kc][bofs]     = pack_fp16(p0, p1);
            Ph[kc][bofs + 1] = pack_fp16(p2, p3);
        }

        // O += P @ V  (single fp16 MMA per fragment pair)
#pragma unroll
        for (int jp = 0; jp < 4; ++jp) {
            float* o0 = O[2 * jp];
            float* o1 = O[2 * jp + 1];
            const int colb = (jp << 4) + vcol_off;
#pragma unroll
            for (int kc = 0; kc < 8; ++kc) {
                const int rowv = (kc << 4) + vrow_off;
                uint32_t vb[4];
                ldsm_x4t(vb, smaddr(&Vh[rowv * kQStr + colb]));
                mma_fp16(o0, Ph[kc], vb);
                mma_fp16(o1, Ph[kc], vb + 2);
            }
        }
        __syncthreads();
    }

    // epilogue
    l0 += __shfl_xor_sync(0xffffffffu, l0, 1);
    l0 += __shfl_xor_sync(0xffffffffu, l0, 2);
    l1 += __shfl_xor_sync(0xffffffffu, l1, 1);
    l1 += __shfl_xor_sync(0xffffffffu, l1, 2);
    const float inv0 = 1.f / l0, inv1 = 1.f / l1;

    const int b_ = bh >> 3, h_ = bh & 7;
    const int grow = q0 + (w << 4) + rq;
    float* cp = g_ctx + ((size_t)b_ * kS + grow) * kH + h_ * kDK + cq;
#pragma unroll
    for (int jn = 0; jn < 8; ++jn) {
        *(float2*)(cp + (jn << 3)) =
            make_float2(O[jn][0] * inv0, O[jn][1] * inv0);
        *(float2*)(cp + (jn << 3) + 8 * kH) =
            make_float2(O[jn][2] * inv1, O[jn][3] * inv1);
    }
}

// ---------------------------------------------------------------------------
extern "C" void kernel_launch(void* const* d_in, const int* in_sizes, int n_in,
                              void* d_out, int out_size)
{
    const float* q  = (const float*)d_in[0];
    const float* k  = (const float*)d_in[1];
    const float* v  = (const float*)d_in[2];
    const float* ab = (const float*)d_in[3];
    const float* Wq = (const float*)d_in[4];
    const float* bq = (const float*)d_in[5];
    const float* Wk = (const float*)d_in[6];
    const float* bk = (const float*)d_in[7];
    const float* Wv = (const float*)d_in[8];
    const float* bv = (const float*)d_in[9];
    const float* Wo = (const float*)d_in[10];
    const float* bo = (const float*)d_in[11];
    float* out = (float*)d_out;

    const int attn_smem = (kTileE + 2 * kStageE) * 2;   // 92160 bytes
    cudaFuncSetAttribute(attn_kernel,
                         cudaFuncAttributeMaxDynamicSharedMemorySize, attn_smem);

    dim3 blk(256);
    qkv_gemm<<<dim3(kH / 128, kM / 128, 3), blk>>>(q, k, v, Wq, Wk, Wv, bq, bk, bv);
    attn_kernel<<<dim3(kS / 128, kB * kNH), blk, attn_smem>>>(ab);
    out_gemm<<<dim3(kH / 128, kM / 128), blk>>>(Wo, bo, out);
}

// round 13
// speedup vs baseline: 1.4573x; 1.0460x over previous
#include <cuda_runtime.h>
#include <cuda_bf16.h>
#include <cuda_fp16.h>
#include <cstdint>

// Problem constants
constexpr int kB  = 2;
constexpr int kS  = 2048;
constexpr int kH  = 512;
constexpr int kNH = 8;
constexpr int kDK = 64;
constexpr int kM  = kB * kS;       // 4096
constexpr float kScale = 0.125f;   // 1/sqrt(64)

constexpr int kHE = kB * kNH * kS * kDK;  // elems per head tensor (2M)

// Scratch (device globals; no allocations allowed)
__device__ __half g_qhi[kHE];               // Q fp16 single (pre-scaled)
__device__ __half g_khi[kHE];               // K fp16 single
__device__ __half g_vhi[kHE];               // V fp16 single
__device__ float  g_ctx[kM * kH];           // [B*S, H]

// ---------------------------------------------------------------------------
// MMA / async-copy helpers
// ---------------------------------------------------------------------------
__device__ __forceinline__ uint32_t smaddr(const void* p) {
    return (uint32_t)__cvta_generic_to_shared(p);
}
__device__ __forceinline__ void ldsm_x4(uint32_t* r, uint32_t a) {
    asm volatile("ldmatrix.sync.aligned.m8n8.x4.shared.b16 {%0,%1,%2,%3},[%4];"
        : "=r"(r[0]), "=r"(r[1]), "=r"(r[2]), "=r"(r[3]) : "r"(a));
}
__device__ __forceinline__ void ldsm_x4t(uint32_t* r, uint32_t a) {
    asm volatile("ldmatrix.sync.aligned.m8n8.x4.trans.shared.b16 {%0,%1,%2,%3},[%4];"
        : "=r"(r[0]), "=r"(r[1]), "=r"(r[2]), "=r"(r[3]) : "r"(a));
}
__device__ __forceinline__ void mma_bf16(float* c, const uint32_t* a,
                                         const uint32_t* b) {
    asm volatile(
        "mma.sync.aligned.m16n8k16.row.col.f32.bf16.bf16.f32 "
        "{%0,%1,%2,%3},{%4,%5,%6,%7},{%8,%9},{%0,%1,%2,%3};"
        : "+f"(c[0]), "+f"(c[1]), "+f"(c[2]), "+f"(c[3])
        : "r"(a[0]), "r"(a[1]), "r"(a[2]), "r"(a[3]), "r"(b[0]), "r"(b[1]));
}
__device__ __forceinline__ void mma_fp16(float* c, const uint32_t* a,
                                         const uint32_t* b) {
    asm volatile(
        "mma.sync.aligned.m16n8k16.row.col.f32.f16.f16.f32 "
        "{%0,%1,%2,%3},{%4,%5,%6,%7},{%8,%9},{%0,%1,%2,%3};"
        : "+f"(c[0]), "+f"(c[1]), "+f"(c[2]), "+f"(c[3])
        : "r"(a[0]), "r"(a[1]), "r"(a[2]), "r"(a[3]), "r"(b[0]), "r"(b[1]));
}
__device__ __forceinline__ uint32_t pack_bf16(float x, float y) {
    __nv_bfloat162 h = __floats2bfloat162_rn(x, y);
    return *reinterpret_cast<uint32_t*>(&h);
}
__device__ __forceinline__ uint32_t pack_fp16(float x, float y) {
    __half2 h = __floats2half2_rn(x, y);
    return *reinterpret_cast<uint32_t*>(&h);
}
__device__ __forceinline__ void split4(float4 v, uint32_t& h0, uint32_t& h1,
                                       uint32_t& l0, uint32_t& l1) {
    __nv_bfloat162 a = __floats2bfloat162_rn(v.x, v.y);
    __nv_bfloat162 b = __floats2bfloat162_rn(v.z, v.w);
    h0 = *reinterpret_cast<uint32_t*>(&a);
    h1 = *reinterpret_cast<uint32_t*>(&b);
    l0 = pack_bf16(v.x - __low2float(a), v.y - __high2float(a));
    l1 = pack_bf16(v.z - __low2float(b), v.w - __high2float(b));
}
__device__ __forceinline__ void cp16(uint32_t dst, const void* src) {
    asm volatile("cp.async.cg.shared.global [%0],[%1],16;"
        :: "r"(dst), "l"(src));
}
__device__ __forceinline__ void cp_commit() {
    asm volatile("cp.async.commit_group;");
}
template <int N>
__device__ __forceinline__ void cp_wait() {
    asm volatile("cp.async.wait_group %0;" :: "n"(N));
}

// ---------------------------------------------------------------------------
// Tensor-core GEMM (R7/R9 proven frame; bf16 3-MMA internal).
// mode 0: Q out fp16 single, scaled. mode 1: K out fp16 single.
// mode 2: V out fp16 single. mode 3: fp32 out.
// ---------------------------------------------------------------------------
constexpr int kXStr = 40;
constexpr int kWStr = 136;

__device__ __forceinline__ void gemm_core(
    const float* __restrict__ X, const float* __restrict__ W,
    const float* __restrict__ bias, float* __restrict__ Yout, int mode)
{
    __shared__ __nv_bfloat16 Xh[128 * kXStr], Xl[128 * kXStr];
    __shared__ __nv_bfloat16 Wh[32 * kWStr],  Wl[32 * kWStr];

    const int tid  = threadIdx.x;
    const int lane = tid & 31, w = tid >> 5;
    const int wm = w >> 1, wn = w & 1;
    const int m0 = blockIdx.y << 7, n0 = blockIdx.x << 7;

    float acc[2][8][4];
#pragma unroll
    for (int mi = 0; mi < 2; ++mi)
#pragma unroll
        for (int jn = 0; jn < 8; ++jn)
#pragma unroll
            for (int i = 0; i < 4; ++i) acc[mi][jn][i] = 0.f;

    const int xr = tid >> 3, xc = (tid & 7) << 2;
    const int wr = tid >> 5, wc = (tid & 31) << 2;

    float4 xs[4], ws[4];
#pragma unroll
    for (int p = 0; p < 4; ++p) {
        xs[p] = *(const float4*)&X[(size_t)(m0 + xr + (p << 5)) * kH + xc];
        ws[p] = *(const float4*)&W[(size_t)(wr + (p << 3)) * kH + n0 + wc];
    }

    for (int k0 = 0; k0 < kH; k0 += 32) {
        __syncthreads();
#pragma unroll
        for (int p = 0; p < 4; ++p) {
            uint32_t h0, h1, l0, l1;
            split4(xs[p], h0, h1, l0, l1);
            const int xo = (xr + (p << 5)) * kXStr + xc;
            *(uint32_t*)&Xh[xo] = h0; *(uint32_t*)&Xh[xo + 2] = h1;
            *(uint32_t*)&Xl[xo] = l0; *(uint32_t*)&Xl[xo + 2] = l1;
            split4(ws[p], h0, h1, l0, l1);
            const int wo = (wr + (p << 3)) * kWStr + wc;
            *(uint32_t*)&Wh[wo] = h0; *(uint32_t*)&Wh[wo + 2] = h1;
            *(uint32_t*)&Wl[wo] = l0; *(uint32_t*)&Wl[wo + 2] = l1;
        }
        __syncthreads();

        if (k0 + 32 < kH) {
#pragma unroll
            for (int p = 0; p < 4; ++p) {
                xs[p] = *(const float4*)&X[(size_t)(m0 + xr + (p << 5)) * kH + k0 + 32 + xc];
                ws[p] = *(const float4*)&W[(size_t)(k0 + 32 + wr + (p << 3)) * kH + n0 + wc];
            }
        }

#pragma unroll
        for (int k16 = 0; k16 < 2; ++k16) {
            uint32_t afh[2][4], afl[2][4];
#pragma unroll
            for (int mi = 0; mi < 2; ++mi) {
                const int row = (wm << 5) + (mi << 4) + (lane & 15);
                const int col = (k16 << 4) + ((lane >> 4) << 3);
                ldsm_x4(afh[mi], smaddr(&Xh[row * kXStr + col]));
                ldsm_x4(afl[mi], smaddr(&Xl[row * kXStr + col]));
            }
#pragma unroll
            for (int jp = 0; jp < 4; ++jp) {
                const int brow = (k16 << 4) + (lane & 15);
                const int bcol = (wn << 6) + (jp << 4) + ((lane >> 4) << 3);
                uint32_t bh[4], bl[4];
                ldsm_x4t(bh, smaddr(&Wh[brow * kWStr + bcol]));
                ldsm_x4t(bl, smaddr(&Wl[brow * kWStr + bcol]));
#pragma unroll
                for (int mi = 0; mi < 2; ++mi) {
                    mma_bf16(acc[mi][2 * jp],     afh[mi], bh);
                    mma_bf16(acc[mi][2 * jp + 1], afh[mi], bh + 2);
                    mma_bf16(acc[mi][2 * jp],     afl[mi], bh);
                    mma_bf16(acc[mi][2 * jp + 1], afl[mi], bh + 2);
                    mma_bf16(acc[mi][2 * jp],     afh[mi], bl);
                    mma_bf16(acc[mi][2 * jp + 1], afh[mi], bl + 2);
                }
            }
        }
    }

#pragma unroll
    for (int jn = 0; jn < 8; ++jn) {
        const int n = n0 + (wn << 6) + (jn << 3) + ((lane & 3) << 1);
        float2 bv = *(const float2*)&bias[n];
#pragma unroll
        for (int mi = 0; mi < 2; ++mi) {
#pragma unroll
            for (int half = 0; half < 2; ++half) {
                const int m = m0 + (wm << 5) + (mi << 4) + (lane >> 2) + (half << 3);
                float v0 = acc[mi][jn][half * 2 + 0] + bv.x;
                float v1 = acc[mi][jn][half * 2 + 1] + bv.y;
                if (mode == 0) { v0 *= kScale; v1 *= kScale; }
                if (mode < 3) {
                    const int b_ = m >> 11;
                    const int s_ = m & (kS - 1);
                    const int h_ = n >> 6;
                    const int d_ = n & (kDK - 1);
                    size_t off = (((size_t)(b_ * kNH + h_)) * kS + s_) * kDK + d_;
                    __half2 hv = __floats2half2_rn(v0, v1);
                    __half* dst = (mode == 0) ? g_qhi : (mode == 1) ? g_khi : g_vhi;
                    *(__half2*)&dst[off] = hv;
                } else {
                    *(float2*)&Yout[(size_t)m * kH + n] = make_float2(v0, v1);
                }
            }
        }
    }
}

__global__ __launch_bounds__(256, 1) void qkv_gemm(
    const float* __restrict__ q, const float* __restrict__ k,
    const float* __restrict__ v,
    const float* __restrict__ Wq, const float* __restrict__ Wk,
    const float* __restrict__ Wv,
    const float* __restrict__ bq, const float* __restrict__ bk,
    const float* __restrict__ bv)
{
    const int mode = blockIdx.z;
    const float* X = (mode == 0) ? q : (mode == 1) ? k : v;
    const float* W = (mode == 0) ? Wq : (mode == 1) ? Wk : Wv;
    const float* B = (mode == 0) ? bq : (mode == 1) ? bk : bv;
    gemm_core(X, W, B, nullptr, mode);
}

__global__ __launch_bounds__(256, 1) void out_gemm(
    const float* __restrict__ Wo, const float* __restrict__ bo,
    float* __restrict__ out)
{
    gemm_core(g_ctx, Wo, bo, out, 3);
}

// ---------------------------------------------------------------------------
// Tensor-core flash attention. R13: occ 2 via half-tile register pipeline.
//  Per kv-128 tile: br0 -> QK0 -> exp0 -> br1 -> QK1 -> PV0 -> exp1 -> PV1.
//  acc/br[8][4], Ph[4][4] (halved footprint) -> fits 2 CTAs/SM.
// stage = Kh, Vh (2 fp16 tiles); smem = (1 + 4) * 18432 B = 92160 B.
// ---------------------------------------------------------------------------
constexpr int kQStr = 72;
constexpr int kTileE = 128 * kQStr;
constexpr int kStageE = 2 * kTileE;           // stage = Kh,Vh

__global__ __launch_bounds__(256, 2) void attn_kernel(const float* __restrict__ bias)
{
    extern __shared__ __half sm[];
    __half* Qh = sm;
    __half* KV = Qh + kTileE;

    const int bh = blockIdx.y;
    const int q0 = blockIdx.x << 7;
    const int tid = threadIdx.x;
    const int lane = tid & 31, w = tid >> 5;

    const size_t hb = (size_t)bh * kS * kDK;
    const __half* Kgh = g_khi + hb;
    const __half* Vgh = g_vhi + hb;
    const float* Bp = bias + (size_t)bh * kS * kS + (size_t)q0 * kS;

    const int r = tid >> 3, c8 = (tid & 7) << 3;

    // stage 0 <- tile 0 (Kh, Vh)
    {
        __half* Kh = KV;
        __half* Vh = Kh + kTileE;
#pragma unroll
        for (int u = 0; u < 4; ++u) {
            const int row = r + (u << 5);
            const size_t g = (size_t)row * kDK + c8;
            const int so = row * kQStr + c8;
            cp16(smaddr(&Kh[so]), &Kgh[g]);
            cp16(smaddr(&Vh[so]), &Vgh[g]);
        }
        cp_commit();
    }

    // Load Q tile (fp16 single)
    {
        const __half* Qgh = g_qhi + hb;
#pragma unroll
        for (int u = 0; u < 4; ++u) {
            const int row = r + (u << 5);
            *(uint4*)&Qh[row * kQStr + c8] =
                *(const uint4*)&Qgh[(size_t)(q0 + row) * kDK + c8];
        }
    }
    __syncthreads();

    // Q fragments (resident)
    uint32_t qf[4][4];
    {
        const int r0 = w << 4;
#pragma unroll
        for (int kc = 0; kc < 4; ++kc) {
            const int row = r0 + (lane & 15);
            const int col = (kc << 4) + ((lane >> 4) << 3);
            ldsm_x4(qf[kc], smaddr(&Qh[row * kQStr + col]));
        }
    }

    float O[8][4];
#pragma unroll
    for (int j = 0; j < 8; j++)
#pragma unroll
        for (int i = 0; i < 4; i++) O[j][i] = 0.f;
    float l0 = 0.f, l1 = 0.f;

    const int rq = lane >> 2;
    const int cq = (lane & 3) << 1;
    const int krow_off = (lane & 7) + ((lane >> 4) << 3);
    const int kcol_off = ((lane >> 3) & 1) << 3;
    const int vrow_off = lane & 15;
    const int vcol_off = (lane >> 4) << 3;

    const float* Bw = Bp + (size_t)((w << 4) + rq) * kS + cq;

    for (int t = 0; t < kS / 128; ++t) {
        const int k0 = t << 7;

        float br[8][4];
        uint32_t Ph[4][4];
        float acc[8][4];

        // bias prefetch for half 0 (kv cols k0 .. k0+63)
#pragma unroll
        for (int jp = 0; jp < 4; ++jp) {
            const float* bp = Bw + k0 + (jp << 4);
            float2 bA0 = __ldcs((const float2*)bp);
            float2 bB0 = __ldcs((const float2*)(bp + 8 * (size_t)kS));
            float2 bA1 = __ldcs((const float2*)(bp + 8));
            float2 bB1 = __ldcs((const float2*)(bp + 8 * (size_t)kS + 8));
            br[2 * jp][0] = bA0.x; br[2 * jp][1] = bA0.y;
            br[2 * jp][2] = bB0.x; br[2 * jp][3] = bB0.y;
            br[2 * jp + 1][0] = bA1.x; br[2 * jp + 1][1] = bA1.y;
            br[2 * jp + 1][2] = bB1.x; br[2 * jp + 1][3] = bB1.y;
        }

        // prefetch K/V tile t+1, wait for tile t
        if (t + 1 < kS / 128) {
            __half* s = KV + ((t + 1) & 1) * kStageE;
            __half* Kh = s;
            __half* Vh = Kh + kTileE;
            const int k0n = (t + 1) << 7;
#pragma unroll
            for (int u = 0; u < 4; ++u) {
                const int row = r + (u << 5);
                const size_t g = (size_t)(k0n + row) * kDK + c8;
                const int so = row * kQStr + c8;
                cp16(smaddr(&Kh[so]), &Kgh[g]);
                cp16(smaddr(&Vh[so]), &Vgh[g]);
            }
            cp_commit();
            cp_wait<1>();
        } else {
            cp_wait<0>();
        }
        __syncthreads();

        __half* s = KV + (t & 1) * kStageE;
        const __half* Kh = s;
        const __half* Vh = Kh + kTileE;

        // ---- QK half 0 (kv cols 0..63 of tile) ----
#pragma unroll
        for (int jp = 0; jp < 4; ++jp) {
            float* a0 = acc[2 * jp];
            float* a1 = acc[2 * jp + 1];
            a0[0] = a0[1] = a0[2] = a0[3] = 0.f;
            a1[0] = a1[1] = a1[2] = a1[3] = 0.f;
            const int rowb = (jp << 4) + krow_off;
#pragma unroll
            for (int kc = 0; kc < 4; ++kc) {
                uint32_t kb[4];
                ldsm_x4(kb, smaddr(&Kh[rowb * kQStr + (kc << 4) + kcol_off]));
                mma_fp16(a0, qf[kc], kb);
                mma_fp16(a1, qf[kc], kb + 2);
            }
        }

        // ---- exp half 0 -> Ph ----
#pragma unroll
        for (int j = 0; j < 8; ++j) {
            float p0 = __expf(acc[j][0] + br[j][0]);
            float p1 = __expf(acc[j][1] + br[j][1]);
            float p2 = __expf(acc[j][2] + br[j][2]);
            float p3 = __expf(acc[j][3] + br[j][3]);
            l0 += p0 + p1;
            l1 += p2 + p3;
            const int kc = j >> 1, bofs = (j & 1) << 1;
            Ph[kc][bofs]     = pack_fp16(p0, p1);
            Ph[kc][bofs + 1] = pack_fp16(p2, p3);
        }

        // ---- bias prefetch half 1 (kv cols 64..127) ----
#pragma unroll
        for (int jp = 0; jp < 4; ++jp) {
            const float* bp = Bw + k0 + ((jp + 4) << 4);
            float2 bA0 = __ldcs((const float2*)bp);
            float2 bB0 = __ldcs((const float2*)(bp + 8 * (size_t)kS));
            float2 bA1 = __ldcs((const float2*)(bp + 8));
            float2 bB1 = __ldcs((const float2*)(bp + 8 * (size_t)kS + 8));
            br[2 * jp][0] = bA0.x; br[2 * jp][1] = bA0.y;
            br[2 * jp][2] = bB0.x; br[2 * jp][3] = bB0.y;
            br[2 * jp + 1][0] = bA1.x; br[2 * jp + 1][1] = bA1.y;
            br[2 * jp + 1][2] = bB1.x; br[2 * jp + 1][3] = bB1.y;
        }

        // ---- QK half 1 (kv cols 64..127) ----
        float acc1[8][4];
#pragma unroll
        for (int jp = 0; jp < 4; ++jp) {
            float* a0 = acc1[2 * jp];
            float* a1 = acc1[2 * jp + 1];
            a0[0] = a0[1] = a0[2] = a0[3] = 0.f;
            a1[0] = a1[1] = a1[2] = a1[3] = 0.f;
            const int rowb = ((jp + 4) << 4) + krow_off;
#pragma unroll
            for (int kc = 0; kc < 4; ++kc) {
                uint32_t kb[4];
                ldsm_x4(kb, smaddr(&Kh[rowb * kQStr + (kc << 4) + kcol_off]));
                mma_fp16(a0, qf[kc], kb);
                mma_fp16(a1, qf[kc], kb + 2);
            }
        }

        // ---- PV half 0 (kv rows 0..63) ----
#pragma unroll
        for (int jp = 0; jp < 4; ++jp) {
            float* o0 = O[2 * jp];
            float* o1 = O[2 * jp + 1];
            const int colb = (jp << 4) + vcol_off;
#pragma unroll
            for (int kc = 0; kc < 4; ++kc) {
                const int rowv = (kc << 4) + vrow_off;
                uint32_t vb[4];
                ldsm_x4t(vb, smaddr(&Vh[rowv * kQStr + colb]));
                mma_fp16(o0, Ph[kc], vb);
                mma_fp16(o1, Ph[kc], vb + 2);
            }
        }

        // ---- exp half 1 -> Ph (reuse) ----
#pragma unroll
        for (int j = 0; j < 8; ++j) {
            float p0 = __expf(acc1[j][0] + br[j][0]);
            float p1 = __expf(acc1[j][1] + br[j][1]);
            float p2 = __expf(acc1[j][2] + br[j][2]);
            float p3 = __expf(acc1[j][3] + br[j][3]);
            l0 += p0 + p1;
            l1 += p2 + p3;
            const int kc = j >> 1, bofs = (j & 1) << 1;
            Ph[kc][bofs]     = pack_fp16(p0, p1);
            Ph[kc][bofs + 1] = pack_fp16(p2, p3);
        }

        // ---- PV half 1 (kv rows 64..127) ----
#pragma unroll
        for (int jp = 0; jp < 4; ++jp) {
            float* o0 = O[2 * jp];
            float* o1 = O[2 * jp + 1];
            const int colb = (jp << 4) + vcol_off;
#pragma unroll
            for (int kc = 0; kc < 4; ++kc) {
                const int rowv = ((kc + 4) << 4) + vrow_off;
                uint32_t vb[4];
                ldsm_x4t(vb, smaddr(&Vh[rowv * kQStr + colb]));
                mma_fp16(o0, Ph[kc], vb);
                mma_fp16(o1, Ph[kc], vb + 2);
            }
        }
        __syncthreads();
    }

    // epilogue
    l0 += __shfl_xor_sync(0xffffffffu, l0, 1);
    l0 += __shfl_xor_sync(0xffffffffu, l0, 2);
    l1 += __shfl_xor_sync(0xffffffffu, l1, 1);
    l1 += __shfl_xor_sync(0xffffffffu, l1, 2);
    const float inv0 = 1.f / l0, inv1 = 1.f / l1;

    const int b_ = bh >> 3, h_ = bh & 7;
    const int grow = q0 + (w << 4) + rq;
    float* cp = g_ctx + ((size_t)b_ * kS + grow) * kH + h_ * kDK + cq;
#pragma unroll
    for (int jn = 0; jn < 8; ++jn) {
        *(float2*)(cp + (jn << 3)) =
            make_float2(O[jn][0] * inv0, O[jn][1] * inv0);
        *(float2*)(cp + (jn << 3) + 8 * kH) =
            make_float2(O[jn][2] * inv1, O[jn][3] * inv1);
    }
}

// ---------------------------------------------------------------------------
extern "C" void kernel_launch(void* const* d_in, const int* in_sizes, int n_in,
                              void* d_out, int out_size)
{
    const float* q  = (const float*)d_in[0];
    const float* k  = (const float*)d_in[1];
    const float* v  = (const float*)d_in[2];
    const float* ab = (const float*)d_in[3];
    const float* Wq = (const float*)d_in[4];
    const float* bq = (const float*)d_in[5];
    const float* Wk = (const float*)d_in[6];
    const float* bk = (const float*)d_in[7];
    const float* Wv = (const float*)d_in[8];
    const float* bv = (const float*)d_in[9];
    const float* Wo = (const float*)d_in[10];
    const float* bo = (const float*)d_in[11];
    float* out = (float*)d_out;

    const int attn_smem = (kTileE + 2 * kStageE) * 2;   // 92160 bytes
    cudaFuncSetAttribute(attn_kernel,
                         cudaFuncAttributeMaxDynamicSharedMemorySize, attn_smem);

    dim3 blk(256);
    qkv_gemm<<<dim3(kH / 128, kM / 128, 3), blk>>>(q, k, v, Wq, Wk, Wv, bq, bk, bv);
    attn_kernel<<<dim3(kS / 128, kB * kNH), blk, attn_smem>>>(ab);
    out_gemm<<<dim3(kH / 128, kM / 128), blk>>>(Wo, bo, out);
}

// round 14
// speedup vs baseline: 1.6702x; 1.1461x over previous
#include <cuda_runtime.h>
#include <cuda_bf16.h>
#include <cuda_fp16.h>
#include <cstdint>

// Problem constants
constexpr int kB  = 2;
constexpr int kS  = 2048;
constexpr int kH  = 512;
constexpr int kNH = 8;
constexpr int kDK = 64;
constexpr int kM  = kB * kS;       // 4096
constexpr float kScale = 0.125f;   // 1/sqrt(64)

constexpr int kHE = kB * kNH * kS * kDK;  // elems per head tensor (2M)

// Scratch (device globals; no allocations allowed)
__device__ __half g_qhi[kHE];               // Q fp16 single (pre-scaled)
__device__ __half g_khi[kHE];               // K fp16 single
__device__ __half g_vhi[kHE];               // V fp16 single
__device__ float  g_ctx[kM * kH];           // [B*S, H]

// ---------------------------------------------------------------------------
// MMA / async-copy helpers
// ---------------------------------------------------------------------------
__device__ __forceinline__ uint32_t smaddr(const void* p) {
    return (uint32_t)__cvta_generic_to_shared(p);
}
__device__ __forceinline__ void ldsm_x4(uint32_t* r, uint32_t a) {
    asm volatile("ldmatrix.sync.aligned.m8n8.x4.shared.b16 {%0,%1,%2,%3},[%4];"
        : "=r"(r[0]), "=r"(r[1]), "=r"(r[2]), "=r"(r[3]) : "r"(a));
}
__device__ __forceinline__ void ldsm_x4t(uint32_t* r, uint32_t a) {
    asm volatile("ldmatrix.sync.aligned.m8n8.x4.trans.shared.b16 {%0,%1,%2,%3},[%4];"
        : "=r"(r[0]), "=r"(r[1]), "=r"(r[2]), "=r"(r[3]) : "r"(a));
}
__device__ __forceinline__ void mma_fp16(float* c, const uint32_t* a,
                                         const uint32_t* b) {
    asm volatile(
        "mma.sync.aligned.m16n8k16.row.col.f32.f16.f16.f32 "
        "{%0,%1,%2,%3},{%4,%5,%6,%7},{%8,%9},{%0,%1,%2,%3};"
        : "+f"(c[0]), "+f"(c[1]), "+f"(c[2]), "+f"(c[3])
        : "r"(a[0]), "r"(a[1]), "r"(a[2]), "r"(a[3]), "r"(b[0]), "r"(b[1]));
}
__device__ __forceinline__ uint32_t pack_fp16(float x, float y) {
    __half2 h = __floats2half2_rn(x, y);
    return *reinterpret_cast<uint32_t*>(&h);
}
// fp16 hi/lo split of float4
__device__ __forceinline__ void split4h(float4 v, uint32_t& h0, uint32_t& h1,
                                        uint32_t& l0, uint32_t& l1) {
    __half2 a = __floats2half2_rn(v.x, v.y);
    __half2 b = __floats2half2_rn(v.z, v.w);
    h0 = *reinterpret_cast<uint32_t*>(&a);
    h1 = *reinterpret_cast<uint32_t*>(&b);
    l0 = pack_fp16(v.x - __half2float(__low2half(a)),
                   v.y - __half2float(__high2half(a)));
    l1 = pack_fp16(v.z - __half2float(__low2half(b)),
                   v.w - __half2float(__high2half(b)));
}
__device__ __forceinline__ void cp16(uint32_t dst, const void* src) {
    asm volatile("cp.async.cg.shared.global [%0],[%1],16;"
        :: "r"(dst), "l"(src));
}
__device__ __forceinline__ void cp_commit() {
    asm volatile("cp.async.commit_group;");
}
template <int N>
__device__ __forceinline__ void cp_wait() {
    asm volatile("cp.async.wait_group %0;" :: "n"(N));
}

// ---------------------------------------------------------------------------
// Tensor-core GEMM, R14: fp16 2-MMA (X hi/lo fp16 x W single fp16).
// mode 0: Q out fp16 single, scaled. mode 1: K. mode 2: V. mode 3: fp32 out.
// ---------------------------------------------------------------------------
constexpr int kXStr = 40;
constexpr int kWStr = 136;

__device__ __forceinline__ void gemm_core(
    const float* __restrict__ X, const float* __restrict__ W,
    const float* __restrict__ bias, float* __restrict__ Yout, int mode)
{
    __shared__ __half Xh[128 * kXStr], Xl[128 * kXStr];
    __shared__ __half Wh[32 * kWStr];

    const int tid  = threadIdx.x;
    const int lane = tid & 31, w = tid >> 5;
    const int wm = w >> 1, wn = w & 1;
    const int m0 = blockIdx.y << 7, n0 = blockIdx.x << 7;

    float acc[2][8][4];
#pragma unroll
    for (int mi = 0; mi < 2; ++mi)
#pragma unroll
        for (int jn = 0; jn < 8; ++jn)
#pragma unroll
            for (int i = 0; i < 4; ++i) acc[mi][jn][i] = 0.f;

    const int xr = tid >> 3, xc = (tid & 7) << 2;
    const int wr = tid >> 5, wc = (tid & 31) << 2;

    float4 xs[4], ws[4];
#pragma unroll
    for (int p = 0; p < 4; ++p) {
        xs[p] = *(const float4*)&X[(size_t)(m0 + xr + (p << 5)) * kH + xc];
        ws[p] = *(const float4*)&W[(size_t)(wr + (p << 3)) * kH + n0 + wc];
    }

    for (int k0 = 0; k0 < kH; k0 += 32) {
        __syncthreads();
#pragma unroll
        for (int p = 0; p < 4; ++p) {
            uint32_t h0, h1, l0, l1;
            split4h(xs[p], h0, h1, l0, l1);
            const int xo = (xr + (p << 5)) * kXStr + xc;
            *(uint32_t*)&Xh[xo] = h0; *(uint32_t*)&Xh[xo + 2] = h1;
            *(uint32_t*)&Xl[xo] = l0; *(uint32_t*)&Xl[xo + 2] = l1;
            __half2 wa = __floats2half2_rn(ws[p].x, ws[p].y);
            __half2 wb = __floats2half2_rn(ws[p].z, ws[p].w);
            const int wo = (wr + (p << 3)) * kWStr + wc;
            *(__half2*)&Wh[wo]     = wa;
            *(__half2*)&Wh[wo + 2] = wb;
        }
        __syncthreads();

        if (k0 + 32 < kH) {
#pragma unroll
            for (int p = 0; p < 4; ++p) {
                xs[p] = *(const float4*)&X[(size_t)(m0 + xr + (p << 5)) * kH + k0 + 32 + xc];
                ws[p] = *(const float4*)&W[(size_t)(k0 + 32 + wr + (p << 3)) * kH + n0 + wc];
            }
        }

#pragma unroll
        for (int k16 = 0; k16 < 2; ++k16) {
            uint32_t afh[2][4], afl[2][4];
#pragma unroll
            for (int mi = 0; mi < 2; ++mi) {
                const int row = (wm << 5) + (mi << 4) + (lane & 15);
                const int col = (k16 << 4) + ((lane >> 4) << 3);
                ldsm_x4(afh[mi], smaddr(&Xh[row * kXStr + col]));
                ldsm_x4(afl[mi], smaddr(&Xl[row * kXStr + col]));
            }
#pragma unroll
            for (int jp = 0; jp < 4; ++jp) {
                const int brow = (k16 << 4) + (lane & 15);
                const int bcol = (wn << 6) + (jp << 4) + ((lane >> 4) << 3);
                uint32_t bh[4];
                ldsm_x4t(bh, smaddr(&Wh[brow * kWStr + bcol]));
#pragma unroll
                for (int mi = 0; mi < 2; ++mi) {
                    mma_fp16(acc[mi][2 * jp],     afh[mi], bh);
                    mma_fp16(acc[mi][2 * jp + 1], afh[mi], bh + 2);
                    mma_fp16(acc[mi][2 * jp],     afl[mi], bh);
                    mma_fp16(acc[mi][2 * jp + 1], afl[mi], bh + 2);
                }
            }
        }
    }

#pragma unroll
    for (int jn = 0; jn < 8; ++jn) {
        const int n = n0 + (wn << 6) + (jn << 3) + ((lane & 3) << 1);
        float2 bv = *(const float2*)&bias[n];
#pragma unroll
        for (int mi = 0; mi < 2; ++mi) {
#pragma unroll
            for (int half = 0; half < 2; ++half) {
                const int m = m0 + (wm << 5) + (mi << 4) + (lane >> 2) + (half << 3);
                float v0 = acc[mi][jn][half * 2 + 0] + bv.x;
                float v1 = acc[mi][jn][half * 2 + 1] + bv.y;
                if (mode == 0) { v0 *= kScale; v1 *= kScale; }
                if (mode < 3) {
                    const int b_ = m >> 11;
                    const int s_ = m & (kS - 1);
                    const int h_ = n >> 6;
                    const int d_ = n & (kDK - 1);
                    size_t off = (((size_t)(b_ * kNH + h_)) * kS + s_) * kDK + d_;
                    __half2 hv = __floats2half2_rn(v0, v1);
                    __half* dst = (mode == 0) ? g_qhi : (mode == 1) ? g_khi : g_vhi;
                    *(__half2*)&dst[off] = hv;
                } else {
                    *(float2*)&Yout[(size_t)m * kH + n] = make_float2(v0, v1);
                }
            }
        }
    }
}

__global__ __launch_bounds__(256, 1) void qkv_gemm(
    const float* __restrict__ q, const float* __restrict__ k,
    const float* __restrict__ v,
    const float* __restrict__ Wq, const float* __restrict__ Wk,
    const float* __restrict__ Wv,
    const float* __restrict__ bq, const float* __restrict__ bk,
    const float* __restrict__ bv)
{
    const int mode = blockIdx.z;
    const float* X = (mode == 0) ? q : (mode == 1) ? k : v;
    const float* W = (mode == 0) ? Wq : (mode == 1) ? Wk : Wv;
    const float* B = (mode == 0) ? bq : (mode == 1) ? bk : bv;
    gemm_core(X, W, B, nullptr, mode);
}

__global__ __launch_bounds__(256, 1) void out_gemm(
    const float* __restrict__ Wo, const float* __restrict__ bo,
    float* __restrict__ out)
{
    gemm_core(g_ctx, Wo, bo, out, 3);
}

// ---------------------------------------------------------------------------
// Tensor-core flash attention (R13, unchanged — occ 2, half-tile pipeline)
// ---------------------------------------------------------------------------
constexpr int kQStr = 72;
constexpr int kTileE = 128 * kQStr;
constexpr int kStageE = 2 * kTileE;           // stage = Kh,Vh

__global__ __launch_bounds__(256, 2) void attn_kernel(const float* __restrict__ bias)
{
    extern __shared__ __half sm[];
    __half* Qh = sm;
    __half* KV = Qh + kTileE;

    const int bh = blockIdx.y;
    const int q0 = blockIdx.x << 7;
    const int tid = threadIdx.x;
    const int lane = tid & 31, w = tid >> 5;

    const size_t hb = (size_t)bh * kS * kDK;
    const __half* Kgh = g_khi + hb;
    const __half* Vgh = g_vhi + hb;
    const float* Bp = bias + (size_t)bh * kS * kS + (size_t)q0 * kS;

    const int r = tid >> 3, c8 = (tid & 7) << 3;

    // stage 0 <- tile 0 (Kh, Vh)
    {
        __half* Kh = KV;
        __half* Vh = Kh + kTileE;
#pragma unroll
        for (int u = 0; u < 4; ++u) {
            const int row = r + (u << 5);
            const size_t g = (size_t)row * kDK + c8;
            const int so = row * kQStr + c8;
            cp16(smaddr(&Kh[so]), &Kgh[g]);
            cp16(smaddr(&Vh[so]), &Vgh[g]);
        }
        cp_commit();
    }

    // Load Q tile (fp16 single)
    {
        const __half* Qgh = g_qhi + hb;
#pragma unroll
        for (int u = 0; u < 4; ++u) {
            const int row = r + (u << 5);
            *(uint4*)&Qh[row * kQStr + c8] =
                *(const uint4*)&Qgh[(size_t)(q0 + row) * kDK + c8];
        }
    }
    __syncthreads();

    // Q fragments (resident)
    uint32_t qf[4][4];
    {
        const int r0 = w << 4;
#pragma unroll
        for (int kc = 0; kc < 4; ++kc) {
            const int row = r0 + (lane & 15);
            const int col = (kc << 4) + ((lane >> 4) << 3);
            ldsm_x4(qf[kc], smaddr(&Qh[row * kQStr + col]));
        }
    }

    float O[8][4];
#pragma unroll
    for (int j = 0; j < 8; j++)
#pragma unroll
        for (int i = 0; i < 4; i++) O[j][i] = 0.f;
    float l0 = 0.f, l1 = 0.f;

    const int rq = lane >> 2;
    const int cq = (lane & 3) << 1;
    const int krow_off = (lane & 7) + ((lane >> 4) << 3);
    const int kcol_off = ((lane >> 3) & 1) << 3;
    const int vrow_off = lane & 15;
    const int vcol_off = (lane >> 4) << 3;

    const float* Bw = Bp + (size_t)((w << 4) + rq) * kS + cq;

    for (int t = 0; t < kS / 128; ++t) {
        const int k0 = t << 7;

        float br[8][4];
        uint32_t Ph[4][4];
        float acc[8][4];

        // bias prefetch for half 0
#pragma unroll
        for (int jp = 0; jp < 4; ++jp) {
            const float* bp = Bw + k0 + (jp << 4);
            float2 bA0 = __ldcs((const float2*)bp);
            float2 bB0 = __ldcs((const float2*)(bp + 8 * (size_t)kS));
            float2 bA1 = __ldcs((const float2*)(bp + 8));
            float2 bB1 = __ldcs((const float2*)(bp + 8 * (size_t)kS + 8));
            br[2 * jp][0] = bA0.x; br[2 * jp][1] = bA0.y;
            br[2 * jp][2] = bB0.x; br[2 * jp][3] = bB0.y;
            br[2 * jp + 1][0] = bA1.x; br[2 * jp + 1][1] = bA1.y;
            br[2 * jp + 1][2] = bB1.x; br[2 * jp + 1][3] = bB1.y;
        }

        // prefetch K/V tile t+1, wait for tile t
        if (t + 1 < kS / 128) {
            __half* s = KV + ((t + 1) & 1) * kStageE;
            __half* Kh = s;
            __half* Vh = Kh + kTileE;
            const int k0n = (t + 1) << 7;
#pragma unroll
            for (int u = 0; u < 4; ++u) {
                const int row = r + (u << 5);
                const size_t g = (size_t)(k0n + row) * kDK + c8;
                const int so = row * kQStr + c8;
                cp16(smaddr(&Kh[so]), &Kgh[g]);
                cp16(smaddr(&Vh[so]), &Vgh[g]);
            }
            cp_commit();
            cp_wait<1>();
        } else {
            cp_wait<0>();
        }
        __syncthreads();

        __half* s = KV + (t & 1) * kStageE;
        const __half* Kh = s;
        const __half* Vh = Kh + kTileE;

        // ---- QK half 0 ----
#pragma unroll
        for (int jp = 0; jp < 4; ++jp) {
            float* a0 = acc[2 * jp];
            float* a1 = acc[2 * jp + 1];
            a0[0] = a0[1] = a0[2] = a0[3] = 0.f;
            a1[0] = a1[1] = a1[2] = a1[3] = 0.f;
            const int rowb = (jp << 4) + krow_off;
#pragma unroll
            for (int kc = 0; kc < 4; ++kc) {
                uint32_t kb[4];
                ldsm_x4(kb, smaddr(&Kh[rowb * kQStr + (kc << 4) + kcol_off]));
                mma_fp16(a0, qf[kc], kb);
                mma_fp16(a1, qf[kc], kb + 2);
            }
        }

        // ---- exp half 0 -> Ph ----
#pragma unroll
        for (int j = 0; j < 8; ++j) {
            float p0 = __expf(acc[j][0] + br[j][0]);
            float p1 = __expf(acc[j][1] + br[j][1]);
            float p2 = __expf(acc[j][2] + br[j][2]);
            float p3 = __expf(acc[j][3] + br[j][3]);
            l0 += p0 + p1;
            l1 += p2 + p3;
            const int kc = j >> 1, bofs = (j & 1) << 1;
            Ph[kc][bofs]     = pack_fp16(p0, p1);
            Ph[kc][bofs + 1] = pack_fp16(p2, p3);
        }

        // ---- bias prefetch half 1 ----
#pragma unroll
        for (int jp = 0; jp < 4; ++jp) {
            const float* bp = Bw + k0 + ((jp + 4) << 4);
            float2 bA0 = __ldcs((const float2*)bp);
            float2 bB0 = __ldcs((const float2*)(bp + 8 * (size_t)kS));
            float2 bA1 = __ldcs((const float2*)(bp + 8));
            float2 bB1 = __ldcs((const float2*)(bp + 8 * (size_t)kS + 8));
            br[2 * jp][0] = bA0.x; br[2 * jp][1] = bA0.y;
            br[2 * jp][2] = bB0.x; br[2 * jp][3] = bB0.y;
            br[2 * jp + 1][0] = bA1.x; br[2 * jp + 1][1] = bA1.y;
            br[2 * jp + 1][2] = bB1.x; br[2 * jp + 1][3] = bB1.y;
        }

        // ---- QK half 1 ----
        float acc1[8][4];
#pragma unroll
        for (int jp = 0; jp < 4; ++jp) {
            float* a0 = acc1[2 * jp];
            float* a1 = acc1[2 * jp + 1];
            a0[0] = a0[1] = a0[2] = a0[3] = 0.f;
            a1[0] = a1[1] = a1[2] = a1[3] = 0.f;
            const int rowb = ((jp + 4) << 4) + krow_off;
#pragma unroll
            for (int kc = 0; kc < 4; ++kc) {
                uint32_t kb[4];
                ldsm_x4(kb, smaddr(&Kh[rowb * kQStr + (kc << 4) + kcol_off]));
                mma_fp16(a0, qf[kc], kb);
                mma_fp16(a1, qf[kc], kb + 2);
            }
        }

        // ---- PV half 0 ----
#pragma unroll
        for (int jp = 0; jp < 4; ++jp) {
            float* o0 = O[2 * jp];
            float* o1 = O[2 * jp + 1];
            const int colb = (jp << 4) + vcol_off;
#pragma unroll
            for (int kc = 0; kc < 4; ++kc) {
                const int rowv = (kc << 4) + vrow_off;
                uint32_t vb[4];
                ldsm_x4t(vb, smaddr(&Vh[rowv * kQStr + colb]));
                mma_fp16(o0, Ph[kc], vb);
                mma_fp16(o1, Ph[kc], vb + 2);
            }
        }

        // ---- exp half 1 -> Ph (reuse) ----
#pragma unroll
        for (int j = 0; j < 8; ++j) {
            float p0 = __expf(acc1[j][0] + br[j][0]);
            float p1 = __expf(acc1[j][1] + br[j][1]);
            float p2 = __expf(acc1[j][2] + br[j][2]);
            float p3 = __expf(acc1[j][3] + br[j][3]);
            l0 += p0 + p1;
            l1 += p2 + p3;
            const int kc = j >> 1, bofs = (j & 1) << 1;
            Ph[kc][bofs]     = pack_fp16(p0, p1);
            Ph[kc][bofs + 1] = pack_fp16(p2, p3);
        }

        // ---- PV half 1 ----
#pragma unroll
        for (int jp = 0; jp < 4; ++jp) {
            float* o0 = O[2 * jp];
            float* o1 = O[2 * jp + 1];
            const int colb = (jp << 4) + vcol_off;
#pragma unroll
            for (int kc = 0; kc < 4; ++kc) {
                const int rowv = ((kc + 4) << 4) + vrow_off;
                uint32_t vb[4];
                ldsm_x4t(vb, smaddr(&Vh[rowv * kQStr + colb]));
                mma_fp16(o0, Ph[kc], vb);
                mma_fp16(o1, Ph[kc], vb + 2);
            }
        }
        __syncthreads();
    }

    // epilogue
    l0 += __shfl_xor_sync(0xffffffffu, l0, 1);
    l0 += __shfl_xor_sync(0xffffffffu, l0, 2);
    l1 += __shfl_xor_sync(0xffffffffu, l1, 1);
    l1 += __shfl_xor_sync(0xffffffffu, l1, 2);
    const float inv0 = 1.f / l0, inv1 = 1.f / l1;

    const int b_ = bh >> 3, h_ = bh & 7;
    const int grow = q0 + (w << 4) + rq;
    float* cp = g_ctx + ((size_t)b_ * kS + grow) * kH + h_ * kDK + cq;
#pragma unroll
    for (int jn = 0; jn < 8; ++jn) {
        *(float2*)(cp + (jn << 3)) =
            make_float2(O[jn][0] * inv0, O[jn][1] * inv0);
        *(float2*)(cp + (jn << 3) + 8 * kH) =
            make_float2(O[jn][2] * inv1, O[jn][3] * inv1);
    }
}

// ---------------------------------------------------------------------------
extern "C" void kernel_launch(void* const* d_in, const int* in_sizes, int n_in,
                              void* d_out, int out_size)
{
    const float* q  = (const float*)d_in[0];
    const float* k  = (const float*)d_in[1];
    const float* v  = (const float*)d_in[2];
    const float* ab = (const float*)d_in[3];
    const float* Wq = (const float*)d_in[4];
    const float* bq = (const float*)d_in[5];
    const float* Wk = (const float*)d_in[6];
    const float* bk = (const float*)d_in[7];
    const float* Wv = (const float*)d_in[8];
    const float* bv = (const float*)d_in[9];
    const float* Wo = (const float*)d_in[10];
    const float* bo = (const float*)d_in[11];
    float* out = (float*)d_out;

    const int attn_smem = (kTileE + 2 * kStageE) * 2;   // 92160 bytes
    cudaFuncSetAttribute(attn_kernel,
                         cudaFuncAttributeMaxDynamicSharedMemorySize, attn_smem);

    dim3 blk(256);
    qkv_gemm<<<dim3(kH / 128, kM / 128, 3), blk>>>(q, k, v, Wq, Wk, Wv, bq, bk, bv);
    attn_kernel<<<dim3(kS / 128, kB * kNH), blk, attn_smem>>>(ab);
    out_gemm<<<dim3(kH / 128, kM / 128), blk>>>(Wo, bo, out);
}